// round 14
// baseline (speedup 1.0000x reference)
#include <cuda_runtime.h>
#include <math.h>
#include <math_constants.h>

#define NS 4760
#define NB 16
#define NT 6
#define NBLK 148
#define FULLM 0xffffffffu

// ------------------------- device scratch -------------------------
__device__ float g_q  [NS*128];
__device__ float g_Wpack[128*328 + 64];
__device__ float g_bpack[328];
__device__ float g_ql [NS*64];
__device__ float g_sp [NS*64];
__device__ float g_spW[NS*64];
__device__ float g_qg [NS*128];
__device__ float g_a0 [NS];
__device__ float g_a1 [NS];
__device__ float g_kg [NB*NT*128];
__device__ float g_vgo [NB*25*128];
__device__ float g_vgoW[NB*25*64];
__device__ float g_sumv[NB*25];
__device__ float g_gram[NB*25*25];
__device__ float g_pgT [(size_t)NS*64*16];   // [n][j][b]
__device__ float g_sg  [NS*32];              // [n][b][2] sumg, sumg2
__device__ float g_G   [(size_t)NS*324];     // per-sensor 18x18 Gram
__device__ float g_S   [NS*16];              // static logits
__device__ float g_ssp [NS*16];              // neighbor sp row-sums
__device__ float g_cst [256];
__device__ float g_xq  [NS*32];              // [n][b][2]
__device__ unsigned g_mb[NS];
__device__ unsigned g_tkt[6];
__device__ unsigned g_barcnt[4];

__device__ __forceinline__ float wsum(float v){
    #pragma unroll
    for (int o=16;o;o>>=1) v += __shfl_xor_sync(FULLM, v, o);
    return v;
}

__device__ __forceinline__ void gbar(int i){
    __syncthreads();
    if (threadIdx.x == 0){
        __threadfence();
        unsigned old = atomicAdd(&g_barcnt[i], 1);
        if (old == NBLK-1){
            atomicExch(&g_barcnt[i], 0);
        } else {
            while (atomicAdd(&g_barcnt[i], 0) != 0) { }
        }
        __threadfence();
    }
    __syncthreads();
}

// ------------------------- the one kernel -------------------------
__global__ void __launch_bounds__(512,1) kAll(
    const float* __restrict__ xf,    const float* __restrict__ latent,
    const float* __restrict__ pos,   const float* __restrict__ femb,
    const float* __restrict__ Wnbr,  const float* __restrict__ bnbr,
    const float* __restrict__ Wql,   const float* __restrict__ bql,
    const float* __restrict__ Wlat,  const float* __restrict__ blat,
    const float* __restrict__ Wlf,   const float* __restrict__ blf,
    const float* __restrict__ Wqg,   const float* __restrict__ bqg,
    const float* __restrict__ Wk,    const float* __restrict__ bk,
    const float* __restrict__ Wv,    const float* __restrict__ bv,
    const float* __restrict__ Wgo,   const float* __restrict__ bgo,
    const float* __restrict__ lng,   const float* __restrict__ lnb,
    const float* __restrict__ Wm1,   const float* __restrict__ bm1,
    const float* __restrict__ Wm2,   const float* __restrict__ bm2,
    const int*   __restrict__ mask,  const int* __restrict__ knn,
    const int*   __restrict__ fid,   float* __restrict__ out)
{
    extern __shared__ float smp[];
    __shared__ int s_t;
    int tid = threadIdx.x;
    int bid = blockIdx.x;
    int lane = tid & 31;
    int wid = tid >> 5;

    // ===================== PHASE A =====================
    if (bid < 96){
        float* lat_s = smp;           // 1056
        float* part  = smp + 1056;    // 512
        float* kv_s  = smp + 1568;    // 128
        float* vg_s  = smp + 1696;    // 128
        int t = bid % NT, b = bid / NT;
        for (int e=tid;e<1024;e+=512) lat_s[e] = latent[((size_t)b*NT+t)*1024 + e];
        if (tid < 32) lat_s[1024+tid] = femb[t*32+tid];
        __syncthreads();
        int j = tid & 127, q = tid >> 7;
        {
            float ac0 = (q==0) ? (blat[j]+blf[j]) : 0.f;
            float ac1 = 0.f, ac2 = 0.f, ac3 = 0.f;
            int i0 = q*256;
            #pragma unroll 4
            for (int i=i0;i<i0+256;i+=4){
                ac0 = fmaf(lat_s[i],   Wlat[(i  )*128+j], ac0);
                ac1 = fmaf(lat_s[i+1], Wlat[(i+1)*128+j], ac1);
                ac2 = fmaf(lat_s[i+2], Wlat[(i+2)*128+j], ac2);
                ac3 = fmaf(lat_s[i+3], Wlat[(i+3)*128+j], ac3);
            }
            float acc = (ac0+ac1)+(ac2+ac3);
            if (q==3){
                for (int f=0;f<32;f++) acc = fmaf(lat_s[1024+f], Wlf[f*128+j], acc);
            }
            part[q*128+j] = acc;
        }
        __syncthreads();
        if (tid < 128) kv_s[tid] = part[tid] + part[128+tid] + part[256+tid] + part[384+tid];
        __syncthreads();
        {
            const float* W = (q < 2) ? Wk : Wv;
            float b0 = 0.f, b1 = 0.f, b2 = 0.f, b3 = 0.f;
            int i0 = (q & 1)*64;
            #pragma unroll 4
            for (int i=i0;i<i0+64;i+=4){
                b0 = fmaf(kv_s[i],   W[(i  )*128+j], b0);
                b1 = fmaf(kv_s[i+1], W[(i+1)*128+j], b1);
                b2 = fmaf(kv_s[i+2], W[(i+2)*128+j], b2);
                b3 = fmaf(kv_s[i+3], W[(i+3)*128+j], b3);
            }
            part[q*128+j] = (b0+b1)+(b2+b3);
        }
        __syncthreads();
        if (tid < 128) g_kg[(b*NT+t)*128 + tid] = part[tid] + part[128+tid] + bk[tid];
        else if (tid < 256){ int jj = tid-128; vg_s[jj] = part[256+jj] + part[384+jj] + bv[jj]; }
        __syncthreads();
        {
            int h = tid >> 7, j2 = tid & 127;
            float a = 0.f;
            #pragma unroll
            for (int d=0;d<32;d++) a = fmaf(vg_s[h*32+d], Wgo[(h*32+d)*128+j2], a);
            g_vgo[((size_t)b*25 + t*4 + h)*128 + j2] = a;
        }
        if (t==0 && tid<128) g_vgo[((size_t)b*25 + 24)*128 + tid] = bgo[tid];
    } else if (bid == 96){
        if (tid < 6) g_tkt[tid] = 0;
        float* W1t = smp;
        for (int e=tid;e<4096;e+=512) W1t[e] = lng[e>>6]*Wm1[e];
        __syncthreads();
        for (int e=tid;e<8192;e+=512){
            int k=e>>6, j=e&63;
            g_Wpack[k*328 + j]      = Wql[e];
            g_Wpack[k*328 + 64 + j] = Wnbr[128+e];
        }
        for (int e=tid;e<16384;e+=512){
            int k=e>>7, j=e&127;
            g_Wpack[k*328 + 128 + j] = Wqg[e];
        }
        for (int e=tid;e<8192;e+=512){
            int c=e>>6, j=e&63;
            float a = 0.f;
            #pragma unroll 4
            for (int i=0;i<64;i++) a = fmaf(Wnbr[128 + c*64 + i], W1t[i*64+j], a);
            g_Wpack[c*328 + 256 + j] = a;
        }
        if (tid < 256){
            int k = tid & 127, which = tid >> 7;
            float a = 0.f;
            for (int i=0;i<64;i++) a = fmaf(Wql[k*64+i], Wnbr[which*64 + i], a);
            g_Wpack[k*328 + 320 + which] = a;
        }
        if (tid < 128){
            for (int c=322;c<328;c++) g_Wpack[tid*328+c] = 0.f;
        }
        if (tid < 64){
            g_bpack[tid]      = bql[tid];
            g_bpack[64+tid]   = bnbr[tid];
            float bf = 0.f;
            for (int i=0;i<64;i++) bf = fmaf(bnbr[i], W1t[i*64+tid], bf);
            g_bpack[256+tid] = bf;
        }
        if (tid < 128) g_bpack[128+tid] = bqg[tid];
        if (tid == 0){
            float a0=0.f, a1=0.f, sw0=0.f, sw1=0.f;
            for (int i=0;i<64;i++){
                a0 = fmaf(bql[i], Wnbr[i], a0); a1 = fmaf(bql[i], Wnbr[64+i], a1);
                sw0 += Wnbr[i]; sw1 += Wnbr[64+i];
            }
            g_bpack[320] = a0; g_bpack[321] = a1;
            g_bpack[322] = sw0; g_bpack[323] = sw1;
        }
        if (tid < 64){
            int j = tid;
            float w0W=0.f, w1W=0.f, gcol=0.f, cadd=0.f;
            for (int i=0;i<192;i++){
                float w = Wm1[i*64+j];
                gcol += lng[i]*w;
                cadd += lnb[i]*w;
            }
            for (int i=0;i<64;i++){
                float w = lng[i]*Wm1[i*64+j];
                w0W += Wnbr[i]     * w;
                w1W += Wnbr[64+i]  * w;
            }
            g_cst[j]      = w0W;
            g_cst[64+j]   = w1W;
            g_cst[128+j]  = gcol;
            g_cst[192+j]  = cadd + bm1[j];
        }
    } else if (bid < 116){
        int n0 = (bid - 97) * 256;
        for (int e=tid;e<256*128;e+=512){
            int s = e>>7, k = e&127, n = n0 + s;
            if (n >= NS) break;
            g_q[n*128 + k] = (k<96) ? pos[n*96+k] : femb[fid[n]*32 + (k-96)];
        }
    } else {
        int tb = bid - 116;
        int nlo = tb*149, nhi = nlo+149; if (nhi > NS) nhi = NS;
        for (int n = nlo + tid; n < nhi; n += 512){
            unsigned mb = 0;
            #pragma unroll
            for (int b=0;b<16;b+=2){
                float2 xa = *(const float2*)(xf + ((size_t)b*NS + n)*2);
                float2 xb = *(const float2*)(xf + ((size_t)(b+1)*NS + n)*2);
                float4 o; o.x=xa.x; o.y=xa.y; o.z=xb.x; o.w=xb.y;
                *(float4*)(g_xq + n*32 + b*2) = o;
                if (mask[b*NS+n])     mb |= (1u<<b);
                if (mask[(b+1)*NS+n]) mb |= (1u<<(b+1));
            }
            g_mb[n] = mb;
        }
    }

    gbar(0);

    // ===================== PHASE B: GEMM tiles + folds =====================
    {
        float* AT = smp;            // 8704
        float* Ws = smp + 8704;     // 8192
        for (;;){
            __syncthreads();
            if (tid == 0) s_t = (int)atomicAdd(&g_tkt[0], 1);
            __syncthreads();
            int tt = s_t;
            if (tt >= 450) break;
            int n0 = (tt/6)*64, c0 = (tt%6)*64;
            for (int e=tid*4;e<8192;e+=2048){
                int s = e>>7, k = e&127, n = n0+s;
                float4 v;
                if (n < NS) v = *(const float4*)(g_q + n*128 + k);
                else { v.x=0.f; v.y=0.f; v.z=0.f; v.w=0.f; }
                AT[(k  )*68 + s] = v.x;
                AT[(k+1)*68 + s] = v.y;
                AT[(k+2)*68 + s] = v.z;
                AT[(k+3)*68 + s] = v.w;
            }
            for (int e=tid*4;e<8192;e+=2048){
                int k = e>>6, cc = e&63;
                *(float4*)(Ws + e) = *(const float4*)(g_Wpack + k*328 + c0 + cc);
            }
            __syncthreads();

            int cg = tid & 15, sg = tid >> 4;
            const float4* Wb = (const float4*)Ws + cg;
            float acc[2][4];
            #pragma unroll
            for (int s=0;s<2;s++){ acc[s][0]=0.f; acc[s][1]=0.f; acc[s][2]=0.f; acc[s][3]=0.f; }
            #pragma unroll 4
            for (int k=0;k<128;k++){
                float4 w = Wb[k*16];
                float a0 = AT[k*68 + sg*2];
                float a1 = AT[k*68 + sg*2 + 1];
                acc[0][0] = fmaf(a0, w.x, acc[0][0]);
                acc[0][1] = fmaf(a0, w.y, acc[0][1]);
                acc[0][2] = fmaf(a0, w.z, acc[0][2]);
                acc[0][3] = fmaf(a0, w.w, acc[0][3]);
                acc[1][0] = fmaf(a1, w.x, acc[1][0]);
                acc[1][1] = fmaf(a1, w.y, acc[1][1]);
                acc[1][2] = fmaf(a1, w.z, acc[1][2]);
                acc[1][3] = fmaf(a1, w.w, acc[1][3]);
            }
            #pragma unroll
            for (int s=0;s<2;s++){
                int n = n0 + sg*2 + s;
                if (n >= NS) continue;
                #pragma unroll
                for (int u=0;u<4;u++){
                    int c = c0 + cg*4 + u;
                    if (c >= 322) continue;
                    float v = acc[s][u] + g_bpack[c];
                    if (c < 64)        g_ql [n*64 + c]        = v;
                    else if (c < 128)  g_sp [n*64 + (c-64)]   = v;
                    else if (c < 256)  g_qg [n*128 + (c-128)] = v;
                    else if (c < 320)  g_spW[n*64 + (c-256)]  = v;
                    else if (c == 320) g_a0[n] = v;
                    else               g_a1[n] = v;
                }
            }
        }
        __syncthreads();
        float* w1bT = smp;   // 8448
        for (int e=tid;e<8192;e+=512){ int c=e>>6, j=e&63; w1bT[j*132+c] = lng[64+c]*Wm1[4096+e]; }
        __syncthreads();
        int c4 = lane*4;
        for (;;){
            int base;
            if (lane == 0) base = (int)atomicAdd(&g_tkt[1], 8);
            base = __shfl_sync(FULLM, base, 0);
            if (base >= 36000) break;
            #pragma unroll
            for (int k8=0;k8<8;k8++){
                int task = base + k8;
                if (task >= 36000) break;
                int b = task/2250, tt2 = task - b*2250;
                if (tt2 < 1600){
                    int i = tt2 >> 6, j = tt2 & 63;
                    float4 a = *(const float4*)(g_vgo + ((size_t)b*25+i)*128 + c4);
                    float4 w = *(const float4*)(w1bT + j*132 + c4);
                    float v = a.x*w.x + a.y*w.y + a.z*w.z + a.w*w.w;
                    v = wsum(v);
                    if (lane==0) g_vgoW[(b*25+i)*64 + j] = v;
                } else if (tt2 < 2225){
                    int p = tt2 - 1600, i1 = p/25, i2 = p - i1*25;
                    float4 a = *(const float4*)(g_vgo + ((size_t)b*25+i1)*128 + c4);
                    float4 c = *(const float4*)(g_vgo + ((size_t)b*25+i2)*128 + c4);
                    float v = a.x*c.x + a.y*c.y + a.z*c.z + a.w*c.w;
                    v = wsum(v);
                    if (lane==0) g_gram[b*625 + p] = v;
                } else {
                    int i = tt2 - 2225;
                    float4 a = *(const float4*)(g_vgo + ((size_t)b*25+i)*128 + c4);
                    float v = a.x + a.y + a.z + a.w;
                    v = wsum(v);
                    if (lane==0) g_sumv[b*25 + i] = v;
                }
            }
        }
    }

    gbar(1);

    // ===================== PHASE B2: per-sensor Gram18 / S / ssp ============
    {
        float* wt = smp + wid*1280;   // 19 rows x 65
        for (;;){
            int n;
            if (lane == 0) n = (int)atomicAdd(&g_tkt[2], 1);
            n = __shfl_sync(FULLM, n, 0);
            if (n >= NS) break;
            int kidx = (lane < 16) ? knn[n*16 + lane] : 0;
            #pragma unroll
            for (int k=0;k<16;k++){
                int j = __shfl_sync(FULLM, kidx, k);
                wt[k*65 + lane]      = g_sp[j*64 + lane];
                wt[k*65 + 32 + lane] = g_sp[j*64 + 32 + lane];
            }
            wt[16*65 + lane] = Wnbr[lane];        wt[16*65 + 32 + lane] = Wnbr[32 + lane];
            wt[17*65 + lane] = Wnbr[64 + lane];   wt[17*65 + 32 + lane] = Wnbr[96 + lane];
            wt[18*65 + lane] = g_ql[n*64 + lane]; wt[18*65 + 32 + lane] = g_ql[n*64 + 32 + lane];
            __syncwarp();
            for (int e=lane;e<356;e+=32){
                const float *r1, *r2;
                if (e < 324){ r1 = wt + (e/18)*65; r2 = wt + (e%18)*65; }
                else if (e < 340){ r1 = wt + (e-324)*65; r2 = wt + 18*65; }
                else { r1 = wt + (e-340)*65; r2 = 0; }
                float a0_=0.f, a1_=0.f, a2_=0.f, a3_=0.f;
                if (r2){
                    #pragma unroll 8
                    for (int c=0;c<64;c+=4){
                        a0_ = fmaf(r1[c],   r2[c],   a0_);
                        a1_ = fmaf(r1[c+1], r2[c+1], a1_);
                        a2_ = fmaf(r1[c+2], r2[c+2], a2_);
                        a3_ = fmaf(r1[c+3], r2[c+3], a3_);
                    }
                } else {
                    #pragma unroll 8
                    for (int c=0;c<64;c+=4){
                        a0_ += r1[c]; a1_ += r1[c+1]; a2_ += r1[c+2]; a3_ += r1[c+3];
                    }
                }
                float v = (a0_+a1_)+(a2_+a3_);
                if (e < 324)      g_G[(size_t)n*324 + e] = v;
                else if (e < 340) g_S[n*16 + (e-324)] = v;
                else              g_ssp[n*16 + (e-340)] = v;
            }
            __syncwarp();
        }
    }

    // ===================== PHASE C: global softmax + Pg =====================
    {
        float* qs     = smp;              // 17024
        float* Ks     = smp + 17024;      // 768
        float* vgoW_s = smp + 17792;      // 1600
        float* gram_s = smp + 19392;      // 700
        float* sumv_s = smp + 20092;      // 32
        float* gax    = smp + 20124;      // 3456
        const float scale = 0.17677669529663687f;
        for (;;){
            __syncthreads();
            if (tid == 0) s_t = (int)atomicAdd(&g_tkt[3], 1);
            __syncthreads();
            int tt = s_t;
            if (tt >= 608) break;
            int b = tt & 15, n0 = (tt >> 4)*128;

            for (int e=tid;e<768;e+=512){
                int r=e>>5, k=e&31, h=r/6, t2=r%6;
                Ks[e] = g_kg[(b*NT+t2)*128 + h*32 + k];
            }
            for (int e=tid;e<1600;e+=512) vgoW_s[e] = g_vgoW[b*1600 + e];
            for (int e=tid;e<625;e+=512){ int i=e/25, jj=e-i*25; gram_s[i*28+jj] = g_gram[b*625 + e]; }
            if (tid < 25) sumv_s[tid] = g_sumv[b*25 + tid];
            for (int e=tid;e<16384;e+=512){
                int s=e>>7, k=e&127;
                int nr = (n0+s < NS) ? (n0+s) : (NS-1);
                qs[s*133+k] = g_qg[nr*128 + k];
            }
            __syncthreads();

            int s = tid & 127, q = tid >> 7;
            {
                float qv[32];
                #pragma unroll
                for (int k=0;k<32;k++) qv[k] = qs[s*133 + q*32 + k];
                float lg[6];
                #pragma unroll
                for (int t2=0;t2<6;t2++){
                    const float* kr = Ks + (q*6+t2)*32;
                    float a = 0.f;
                    #pragma unroll
                    for (int k=0;k<32;k++) a = fmaf(qv[k], kr[k], a);
                    lg[t2] = a;
                }
                float m = lg[0];
                #pragma unroll
                for (int t2=1;t2<6;t2++) m = fmaxf(m, lg[t2]);
                float den = 0.f, ex[6];
                #pragma unroll
                for (int t2=0;t2<6;t2++){ ex[t2] = __expf((lg[t2]-m)*scale); den += ex[t2]; }
                float inv = 1.f/den;
                #pragma unroll
                for (int t2=0;t2<6;t2++) gax[s*27 + t2*4 + q] = ex[t2]*inv;
            }
            __syncthreads();

            float ga[25];
            #pragma unroll
            for (int i=0;i<24;i++) ga[i] = gax[s*27 + i];
            ga[24] = 1.f;

            float4 pg4[4];
            {
                const float4* w24 = (const float4*)(vgoW_s + 24*64 + q*16);
                #pragma unroll
                for (int jj=0;jj<4;jj++) pg4[jj] = w24[jj];
            }
            #pragma unroll
            for (int i=0;i<24;i++){
                float g = ga[i];
                const float4* wr = (const float4*)(vgoW_s + i*64 + q*16);
                #pragma unroll
                for (int jj=0;jj<4;jj++){
                    float4 w = wr[jj];
                    pg4[jj].x = fmaf(g, w.x, pg4[jj].x);
                    pg4[jj].y = fmaf(g, w.y, pg4[jj].y);
                    pg4[jj].z = fmaf(g, w.z, pg4[jj].z);
                    pg4[jj].w = fmaf(g, w.w, pg4[jj].w);
                }
            }
            float sumg = 0.f, sumg2 = 0.f;
            if (q == 0){
                sumg = sumv_s[24];
                #pragma unroll
                for (int i=0;i<24;i++) sumg = fmaf(ga[i], sumv_s[i], sumg);
            }
            if (q == 1){
                #pragma unroll
                for (int i=0;i<25;i++){
                    float ti = gram_s[i*28 + 24];
                    #pragma unroll
                    for (int j4=0;j4<6;j4++){
                        float4 gv = *(const float4*)(gram_s + i*28 + j4*4);
                        ti = fmaf(gv.x, ga[j4*4+0], ti);
                        ti = fmaf(gv.y, ga[j4*4+1], ti);
                        ti = fmaf(gv.z, ga[j4*4+2], ti);
                        ti = fmaf(gv.w, ga[j4*4+3], ti);
                    }
                    sumg2 = fmaf(ga[i], ti, sumg2);
                }
            }
            if (n0 + s < NS){
                int n = n0 + s;
                float* dst = g_pgT + (size_t)n*1024 + b;
                #pragma unroll
                for (int jj=0;jj<4;jj++){
                    int j = q*16 + jj*4;
                    dst[(j  )*16] = pg4[jj].x;
                    dst[(j+1)*16] = pg4[jj].y;
                    dst[(j+2)*16] = pg4[jj].z;
                    dst[(j+3)*16] = pg4[jj].w;
                }
                if (q == 0) g_sg[n*32 + b*2]     = sumg;
                if (q == 1) g_sg[n*32 + b*2 + 1] = sumg2;
            }
        }
    }

    gbar(2);

    // ===================== PHASE D: lane-per-(n,b), reduction-free ==========
    {
        float* cst = smp;                 // 384: w0W w1W gcol cadd wm2(64) + pad
        float* wsp = smp + 384 + wid*1472;
        if (tid < 256) cst[tid] = g_cst[tid];
        if (tid >= 256 && tid < 320) cst[tid] = Wm2[tid-256];
        __syncthreads();
        float sw0 = g_bpack[322], sw1 = g_bpack[323], bm2v = bm2[0];

        int b = lane & 15, jh = lane >> 4;
        float* M    = wsp;          // 16 x 65
        float* Gs   = wsp + 1040;   // 324
        float* Ss   = wsp + 1364;   // 16
        float* sspS = wsp + 1380;   // 16
        int*   kix  = (int*)(wsp + 1396);  // 16

        for (;;){
            int n;
            if (lane == 0) n = (int)atomicAdd(&g_tkt[4], 1);
            n = __shfl_sync(FULLM, n, 0);
            if (n >= NS) break;

            if (lane < 16) kix[lane] = knn[n*16 + lane];
            __syncwarp();
            #pragma unroll
            for (int k=0;k<16;k++){
                int j = kix[k];
                M[k*65 + lane]      = g_spW[j*64 + lane];
                M[k*65 + 32 + lane] = g_spW[j*64 + 32 + lane];
            }
            for (int e=lane;e<324;e+=32) Gs[e] = g_G[(size_t)n*324 + e];
            if (lane < 16){ Ss[lane] = g_S[n*16 + lane]; sspS[lane] = g_ssp[n*16 + lane]; }
            __syncwarp();

            unsigned mbn = g_mb[n];
            float a0 = g_a0[n], a1 = g_a1[n];
            float sgv  = g_sg[n*32 + b*2];
            float sg2v = g_sg[n*32 + b*2 + 1];

            float u[18];
            float den = 0.f, alp = 0.f, bet = 0.f;
            #pragma unroll
            for (int k=0;k<16;k++){
                int j = kix[k];
                float2 xv = *(const float2*)(g_xq + j*32 + b*2);
                unsigned mk = g_mb[j];
                float l = (Ss[k] + xv.x*a0 + xv.y*a1)*0.125f;
                float e = ((mk >> b) & 1u) ? 1e-20f : __expf(l);
                u[k] = e;
                den += e;
                alp = fmaf(e, xv.x, alp);
                bet = fmaf(e, xv.y, bet);
            }
            float inv = 1.f/den;
            alp *= inv; bet *= inv;
            #pragma unroll
            for (int k=0;k<16;k++) u[k] *= inv;
            u[16] = alp; u[17] = bet;

            float sL = alp*sw0 + bet*sw1;
            #pragma unroll
            for (int k=0;k<16;k++) sL = fmaf(u[k], sspS[k], sL);

            float sL2 = 0.f;
            #pragma unroll
            for (int i=0;i<18;i++){
                const float* gr = Gs + i*18;
                float r0 = 0.f, r1 = 0.f;
                #pragma unroll
                for (int jx=0;jx<18;jx+=2){
                    r0 = fmaf(gr[jx],   u[jx],   r0);
                    r1 = fmaf(gr[jx+1], u[jx+1], r1);
                }
                sL2 = fmaf(u[i], r0+r1, sL2);
            }

            float mean = (sL + sgv)*(1.f/192.f);
            float var  = (sL2 + sg2v)*(1.f/192.f) - mean*mean;
            float rstd = rsqrtf(var + 1e-5f);

            float pr = 0.f;
            const float* pgT = g_pgT + (size_t)n*1024 + b;
            #pragma unroll
            for (int jj=0;jj<32;jj++){
                int j = jh*32 + jj;
                float Pj = fmaf(alp, cst[j], bet*cst[64+j]);
                #pragma unroll
                for (int k=0;k<16;k++) Pj = fmaf(u[k], M[k*65 + j], Pj);
                float Pgj = pgT[j*16];
                float h = fmaf(rstd, (Pj + Pgj) - mean*cst[128+j], cst[192+j]);
                float g = 0.5f*h*(1.f + erff(h*0.70710678118654752f));
                pr = fmaf(g, cst[256+j], pr);
            }
            pr += __shfl_xor_sync(FULLM, pr, 16);
            if (jh == 0){
                out[b*NS + n] = ((mbn >> b) & 1u) ? (pr + bm2v) : 0.f;
            }
        }
    }
}

// ------------------------- launch -------------------------
extern "C" void kernel_launch(void* const* d_in, const int* in_sizes, int n_in,
                              void* d_out, int out_size){
    const float* xf    = (const float*)d_in[0];
    const float* latent= (const float*)d_in[1];
    const float* pos   = (const float*)d_in[2];
    const float* femb  = (const float*)d_in[3];
    const float* Wnbr  = (const float*)d_in[4];
    const float* bnbr  = (const float*)d_in[5];
    const float* Wql   = (const float*)d_in[6];
    const float* bql   = (const float*)d_in[7];
    const float* Wlat  = (const float*)d_in[8];
    const float* blat  = (const float*)d_in[9];
    const float* Wlf   = (const float*)d_in[10];
    const float* blf   = (const float*)d_in[11];
    const float* Wqg   = (const float*)d_in[12];
    const float* bqg   = (const float*)d_in[13];
    const float* Wk    = (const float*)d_in[14];
    const float* bk    = (const float*)d_in[15];
    const float* Wv    = (const float*)d_in[16];
    const float* bv    = (const float*)d_in[17];
    const float* Wgo   = (const float*)d_in[18];
    const float* bgo   = (const float*)d_in[19];
    const float* lng   = (const float*)d_in[20];
    const float* lnb   = (const float*)d_in[21];
    const float* Wm1   = (const float*)d_in[22];
    const float* bm1   = (const float*)d_in[23];
    const float* Wm2   = (const float*)d_in[24];
    const float* bm2   = (const float*)d_in[25];
    const int* mask    = (const int*)d_in[26];
    const int* knn     = (const int*)d_in[27];
    const int* fid     = (const int*)d_in[28];
    float* out = (float*)d_out;

    static int smem_sz = 24576*4;
    cudaFuncSetAttribute(kAll, cudaFuncAttributeMaxDynamicSharedMemorySize, smem_sz);

    kAll<<<NBLK, 512, smem_sz>>>(
        xf, latent, pos, femb, Wnbr, bnbr, Wql, bql, Wlat, blat, Wlf, blf,
        Wqg, bqg, Wk, bk, Wv, bv, Wgo, bgo, lng, lnb, Wm1, bm1, Wm2, bm2,
        mask, knn, fid, out);
}

// round 15
// speedup vs baseline: 1.0641x; 1.0641x over previous
#include <cuda_runtime.h>
#include <math.h>
#include <math_constants.h>

#define NS 4760
#define NB 16
#define NT 6
#define NBLK 296
#define FULLM 0xffffffffu

// ------------------------- device scratch -------------------------
__device__ float g_q  [NS*128];
__device__ float g_Wpack[128*328 + 64];
__device__ float g_bpack[328];
__device__ float g_ql [NS*64];
__device__ float g_sp [NS*64];
__device__ float g_spW[NS*64];
__device__ float g_qg [NS*128];
__device__ float g_a0 [NS];
__device__ float g_a1 [NS];
__device__ float g_kg [NB*NT*128];
__device__ float g_vgo [NB*25*128];
__device__ float g_vgoW[NB*25*64];
__device__ float g_sumv[NB*25];
__device__ float g_gram[NB*25*25];
__device__ float g_pg  [(size_t)NB*NS*68];   // [b][n][68]
__device__ float g_cst [256];
__device__ float g_xq  [NS*32];              // [n][b][2]
__device__ unsigned g_mb[NS];
__device__ unsigned g_tkt[4];
__device__ unsigned g_barcnt[4];

__device__ __forceinline__ float wsum(float v){
    #pragma unroll
    for (int o=16;o;o>>=1) v += __shfl_xor_sync(FULLM, v, o);
    return v;
}
template<int N>
__device__ __forceinline__ void wsumv(float* v){
    #pragma unroll
    for (int o=16;o;o>>=1){
        #pragma unroll
        for (int i=0;i<N;i++) v[i] += __shfl_xor_sync(FULLM, v[i], o);
    }
}

__device__ __forceinline__ void gbar(int i){
    __syncthreads();
    if (threadIdx.x == 0){
        __threadfence();
        unsigned old = atomicAdd(&g_barcnt[i], 1);
        if (old == NBLK-1){
            atomicExch(&g_barcnt[i], 0);
        } else {
            while (atomicAdd(&g_barcnt[i], 0) != 0) { }
        }
        __threadfence();
    }
    __syncthreads();
}

// ------------------------- the one kernel (2 CTA/SM, 64 regs) -------------
__global__ void __launch_bounds__(512,2) kAll(
    const float* __restrict__ xf,    const float* __restrict__ latent,
    const float* __restrict__ pos,   const float* __restrict__ femb,
    const float* __restrict__ Wnbr,  const float* __restrict__ bnbr,
    const float* __restrict__ Wql,   const float* __restrict__ bql,
    const float* __restrict__ Wlat,  const float* __restrict__ blat,
    const float* __restrict__ Wlf,   const float* __restrict__ blf,
    const float* __restrict__ Wqg,   const float* __restrict__ bqg,
    const float* __restrict__ Wk,    const float* __restrict__ bk,
    const float* __restrict__ Wv,    const float* __restrict__ bv,
    const float* __restrict__ Wgo,   const float* __restrict__ bgo,
    const float* __restrict__ lng,   const float* __restrict__ lnb,
    const float* __restrict__ Wm1,   const float* __restrict__ bm1,
    const float* __restrict__ Wm2,   const float* __restrict__ bm2,
    const int*   __restrict__ mask,  const int* __restrict__ knn,
    const int*   __restrict__ fid,   float* __restrict__ out)
{
    extern __shared__ float smp[];
    __shared__ int s_t;
    int tid = threadIdx.x;
    int bid = blockIdx.x;
    int lane = tid & 31;

    // ===================== PHASE A =====================
    if (bid < 96){
        float* lat_s = smp;           // 1056
        float* part  = smp + 1056;    // 512
        float* kv_s  = smp + 1568;    // 128
        float* vg_s  = smp + 1696;    // 128
        int t = bid % NT, b = bid / NT;
        for (int e=tid;e<1024;e+=512) lat_s[e] = latent[((size_t)b*NT+t)*1024 + e];
        if (tid < 32) lat_s[1024+tid] = femb[t*32+tid];
        __syncthreads();
        int j = tid & 127, q = tid >> 7;
        {
            float ac0 = (q==0) ? (blat[j]+blf[j]) : 0.f;
            float ac1 = 0.f, ac2 = 0.f, ac3 = 0.f;
            int i0 = q*256;
            #pragma unroll 4
            for (int i=i0;i<i0+256;i+=4){
                ac0 = fmaf(lat_s[i],   Wlat[(i  )*128+j], ac0);
                ac1 = fmaf(lat_s[i+1], Wlat[(i+1)*128+j], ac1);
                ac2 = fmaf(lat_s[i+2], Wlat[(i+2)*128+j], ac2);
                ac3 = fmaf(lat_s[i+3], Wlat[(i+3)*128+j], ac3);
            }
            float acc = (ac0+ac1)+(ac2+ac3);
            if (q==3){
                for (int f=0;f<32;f++) acc = fmaf(lat_s[1024+f], Wlf[f*128+j], acc);
            }
            part[q*128+j] = acc;
        }
        __syncthreads();
        if (tid < 128) kv_s[tid] = part[tid] + part[128+tid] + part[256+tid] + part[384+tid];
        __syncthreads();
        {
            const float* W = (q < 2) ? Wk : Wv;
            float b0 = 0.f, b1 = 0.f, b2 = 0.f, b3 = 0.f;
            int i0 = (q & 1)*64;
            #pragma unroll 4
            for (int i=i0;i<i0+64;i+=4){
                b0 = fmaf(kv_s[i],   W[(i  )*128+j], b0);
                b1 = fmaf(kv_s[i+1], W[(i+1)*128+j], b1);
                b2 = fmaf(kv_s[i+2], W[(i+2)*128+j], b2);
                b3 = fmaf(kv_s[i+3], W[(i+3)*128+j], b3);
            }
            part[q*128+j] = (b0+b1)+(b2+b3);
        }
        __syncthreads();
        if (tid < 128) g_kg[(b*NT+t)*128 + tid] = part[tid] + part[128+tid] + bk[tid];
        else if (tid < 256){ int jj = tid-128; vg_s[jj] = part[256+jj] + part[384+jj] + bv[jj]; }
        __syncthreads();
        {
            int h = tid >> 7, j2 = tid & 127;
            float a = 0.f;
            #pragma unroll
            for (int d=0;d<32;d++) a = fmaf(vg_s[h*32+d], Wgo[(h*32+d)*128+j2], a);
            g_vgo[((size_t)b*25 + t*4 + h)*128 + j2] = a;
        }
        if (t==0 && tid<128) g_vgo[((size_t)b*25 + 24)*128 + tid] = bgo[tid];
    } else if (bid == 96){
        if (tid == 0){ g_tkt[0]=0; g_tkt[1]=0; g_tkt[2]=0; g_tkt[3]=0; }
        float* W1t = smp;
        for (int e=tid;e<4096;e+=512) W1t[e] = lng[e>>6]*Wm1[e];
        __syncthreads();
        for (int e=tid;e<8192;e+=512){
            int k=e>>6, j=e&63;
            g_Wpack[k*328 + j]      = Wql[e];
            g_Wpack[k*328 + 64 + j] = Wnbr[128+e];
        }
        for (int e=tid;e<16384;e+=512){
            int k=e>>7, j=e&127;
            g_Wpack[k*328 + 128 + j] = Wqg[e];
        }
        for (int e=tid;e<8192;e+=512){
            int c=e>>6, j=e&63;
            float a = 0.f;
            #pragma unroll 4
            for (int i=0;i<64;i++) a = fmaf(Wnbr[128 + c*64 + i], W1t[i*64+j], a);
            g_Wpack[c*328 + 256 + j] = a;
        }
        if (tid < 256){
            int k = tid & 127, which = tid >> 7;
            float a = 0.f;
            for (int i=0;i<64;i++) a = fmaf(Wql[k*64+i], Wnbr[which*64 + i], a);
            g_Wpack[k*328 + 320 + which] = a;
        }
        if (tid < 128){
            for (int c=322;c<328;c++) g_Wpack[tid*328+c] = 0.f;
        }
        if (tid < 64){
            g_bpack[tid]      = bql[tid];
            g_bpack[64+tid]   = bnbr[tid];
            float bf = 0.f;
            for (int i=0;i<64;i++) bf = fmaf(bnbr[i], W1t[i*64+tid], bf);
            g_bpack[256+tid] = bf;
        }
        if (tid < 128) g_bpack[128+tid] = bqg[tid];
        if (tid == 0){
            float a0=0.f, a1=0.f;
            for (int i=0;i<64;i++){ a0 = fmaf(bql[i], Wnbr[i], a0); a1 = fmaf(bql[i], Wnbr[64+i], a1); }
            g_bpack[320] = a0; g_bpack[321] = a1;
        }
        if (tid < 64){
            int j = tid;
            float w0W=0.f, w1W=0.f, gcol=0.f, cadd=0.f;
            for (int i=0;i<192;i++){
                float w = Wm1[i*64+j];
                gcol += lng[i]*w;
                cadd += lnb[i]*w;
            }
            for (int i=0;i<64;i++){
                float w = lng[i]*Wm1[i*64+j];
                w0W += Wnbr[i]     * w;
                w1W += Wnbr[64+i]  * w;
            }
            g_cst[j]      = w0W;
            g_cst[64+j]   = w1W;
            g_cst[128+j]  = gcol;
            g_cst[192+j]  = cadd + bm1[j];
        }
    } else if (bid < 116){
        int n0 = (bid - 97) * 256;
        for (int e=tid;e<256*128;e+=512){
            int s = e>>7, k = e&127, n = n0 + s;
            if (n >= NS) break;
            g_q[n*128 + k] = (k<96) ? pos[n*96+k] : femb[fid[n]*32 + (k-96)];
        }
    } else if (bid < 148){
        int tb = bid - 116;
        int nlo = tb*149, nhi = nlo+149; if (nhi > NS) nhi = NS;
        for (int n = nlo + tid; n < nhi; n += 512){
            unsigned mb = 0;
            #pragma unroll
            for (int b=0;b<16;b+=2){
                float2 xa = *(const float2*)(xf + ((size_t)b*NS + n)*2);
                float2 xb = *(const float2*)(xf + ((size_t)(b+1)*NS + n)*2);
                float4 o; o.x=xa.x; o.y=xa.y; o.z=xb.x; o.w=xb.y;
                *(float4*)(g_xq + n*32 + b*2) = o;
                if (mask[b*NS+n])     mb |= (1u<<b);
                if (mask[(b+1)*NS+n]) mb |= (1u<<(b+1));
            }
            g_mb[n] = mb;
        }
    }

    gbar(0);

    // ===================== PHASE B: GEMM tiles + folds =====================
    {
        float* AT = smp;            // 8704
        float* Ws = smp + 8704;     // 8192
        for (;;){
            __syncthreads();
            if (tid == 0) s_t = (int)atomicAdd(&g_tkt[0], 1);
            __syncthreads();
            int tt = s_t;
            if (tt >= 450) break;
            int n0 = (tt/6)*64, c0 = (tt%6)*64;
            for (int e=tid*4;e<8192;e+=2048){
                int s = e>>7, k = e&127, n = n0+s;
                float4 v;
                if (n < NS) v = *(const float4*)(g_q + n*128 + k);
                else { v.x=0.f; v.y=0.f; v.z=0.f; v.w=0.f; }
                AT[(k  )*68 + s] = v.x;
                AT[(k+1)*68 + s] = v.y;
                AT[(k+2)*68 + s] = v.z;
                AT[(k+3)*68 + s] = v.w;
            }
            for (int e=tid*4;e<8192;e+=2048){
                int k = e>>6, cc = e&63;
                *(float4*)(Ws + e) = *(const float4*)(g_Wpack + k*328 + c0 + cc);
            }
            __syncthreads();

            int cg = tid & 15, sg = tid >> 4;
            const float4* Wb = (const float4*)Ws + cg;
            float acc[2][4];
            #pragma unroll
            for (int s=0;s<2;s++){ acc[s][0]=0.f; acc[s][1]=0.f; acc[s][2]=0.f; acc[s][3]=0.f; }
            #pragma unroll 4
            for (int k=0;k<128;k++){
                float4 w = Wb[k*16];
                float a0 = AT[k*68 + sg*2];
                float a1 = AT[k*68 + sg*2 + 1];
                acc[0][0] = fmaf(a0, w.x, acc[0][0]);
                acc[0][1] = fmaf(a0, w.y, acc[0][1]);
                acc[0][2] = fmaf(a0, w.z, acc[0][2]);
                acc[0][3] = fmaf(a0, w.w, acc[0][3]);
                acc[1][0] = fmaf(a1, w.x, acc[1][0]);
                acc[1][1] = fmaf(a1, w.y, acc[1][1]);
                acc[1][2] = fmaf(a1, w.z, acc[1][2]);
                acc[1][3] = fmaf(a1, w.w, acc[1][3]);
            }
            #pragma unroll
            for (int s=0;s<2;s++){
                int n = n0 + sg*2 + s;
                if (n >= NS) continue;
                #pragma unroll
                for (int u=0;u<4;u++){
                    int c = c0 + cg*4 + u;
                    if (c >= 322) continue;
                    float v = acc[s][u] + g_bpack[c];
                    if (c < 64)        g_ql [n*64 + c]        = v;
                    else if (c < 128)  g_sp [n*64 + (c-64)]   = v;
                    else if (c < 256)  g_qg [n*128 + (c-128)] = v;
                    else if (c < 320)  g_spW[n*64 + (c-256)]  = v;
                    else if (c == 320) g_a0[n] = v;
                    else               g_a1[n] = v;
                }
            }
        }
        __syncthreads();
        float* w1bT = smp;   // 8448
        for (int e=tid;e<8192;e+=512){ int c=e>>6, j=e&63; w1bT[j*132+c] = lng[64+c]*Wm1[4096+e]; }
        __syncthreads();
        int c4 = lane*4;
        for (;;){
            int base;
            if (lane == 0) base = (int)atomicAdd(&g_tkt[1], 8);
            base = __shfl_sync(FULLM, base, 0);
            if (base >= 36000) break;
            #pragma unroll
            for (int k8=0;k8<8;k8++){
                int task = base + k8;
                if (task >= 36000) break;
                int b = task/2250, tt2 = task - b*2250;
                if (tt2 < 1600){
                    int i = tt2 >> 6, j = tt2 & 63;
                    float4 a = *(const float4*)(g_vgo + ((size_t)b*25+i)*128 + c4);
                    float4 w = *(const float4*)(w1bT + j*132 + c4);
                    float v = a.x*w.x + a.y*w.y + a.z*w.z + a.w*w.w;
                    v = wsum(v);
                    if (lane==0) g_vgoW[(b*25+i)*64 + j] = v;
                } else if (tt2 < 2225){
                    int p = tt2 - 1600, i1 = p/25, i2 = p - i1*25;
                    float4 a = *(const float4*)(g_vgo + ((size_t)b*25+i1)*128 + c4);
                    float4 c = *(const float4*)(g_vgo + ((size_t)b*25+i2)*128 + c4);
                    float v = a.x*c.x + a.y*c.y + a.z*c.z + a.w*c.w;
                    v = wsum(v);
                    if (lane==0) g_gram[b*625 + p] = v;
                } else {
                    int i = tt2 - 2225;
                    float4 a = *(const float4*)(g_vgo + ((size_t)b*25+i)*128 + c4);
                    float v = a.x + a.y + a.z + a.w;
                    v = wsum(v);
                    if (lane==0) g_sumv[b*25 + i] = v;
                }
            }
        }
    }

    gbar(1);

    // ===================== PHASE C: global softmax + Pg =====================
    {
        float* qs     = smp;              // 17024
        float* Ks     = smp + 17024;      // 768
        float* vgoW_s = smp + 17792;      // 1600
        float* gram_s = smp + 19392;      // 700
        float* sumv_s = smp + 20092;      // 32
        float* gax    = smp + 20124;      // 3456
        const float scale = 0.17677669529663687f;
        for (;;){
            __syncthreads();
            if (tid == 0) s_t = (int)atomicAdd(&g_tkt[2], 1);
            __syncthreads();
            int tt = s_t;
            if (tt >= 608) break;
            int b = tt & 15, n0 = (tt >> 4)*128;

            for (int e=tid;e<768;e+=512){
                int r=e>>5, k=e&31, h=r/6, t2=r%6;
                Ks[e] = g_kg[(b*NT+t2)*128 + h*32 + k];
            }
            for (int e=tid;e<1600;e+=512) vgoW_s[e] = g_vgoW[b*1600 + e];
            for (int e=tid;e<625;e+=512){ int i=e/25, jj=e-i*25; gram_s[i*28+jj] = g_gram[b*625 + e]; }
            if (tid < 25) sumv_s[tid] = g_sumv[b*25 + tid];
            for (int e=tid;e<16384;e+=512){
                int s=e>>7, k=e&127;
                int nr = (n0+s < NS) ? (n0+s) : (NS-1);
                qs[s*133+k] = g_qg[nr*128 + k];
            }
            __syncthreads();

            int s = tid & 127, q = tid >> 7;
            {
                float lg[6];
                #pragma unroll
                for (int t2=0;t2<6;t2++){
                    const float* kr = Ks + (q*6+t2)*32;
                    const float* qv = qs + s*133 + q*32;
                    float a0_=0.f, a1_=0.f, a2_=0.f, a3_=0.f;
                    #pragma unroll 8
                    for (int k=0;k<32;k+=4){
                        a0_ = fmaf(qv[k],   kr[k],   a0_);
                        a1_ = fmaf(qv[k+1], kr[k+1], a1_);
                        a2_ = fmaf(qv[k+2], kr[k+2], a2_);
                        a3_ = fmaf(qv[k+3], kr[k+3], a3_);
                    }
                    lg[t2] = (a0_+a1_)+(a2_+a3_);
                }
                float m = lg[0];
                #pragma unroll
                for (int t2=1;t2<6;t2++) m = fmaxf(m, lg[t2]);
                float den = 0.f, ex[6];
                #pragma unroll
                for (int t2=0;t2<6;t2++){ ex[t2] = __expf((lg[t2]-m)*scale); den += ex[t2]; }
                float inv = 1.f/den;
                #pragma unroll
                for (int t2=0;t2<6;t2++) gax[s*27 + t2*4 + q] = ex[t2]*inv;
            }
            __syncthreads();

            float4 pg4[4];
            {
                const float4* w24 = (const float4*)(vgoW_s + 24*64 + q*16);
                #pragma unroll
                for (int jj=0;jj<4;jj++) pg4[jj] = w24[jj];
            }
            #pragma unroll
            for (int i=0;i<24;i++){
                float g = gax[s*27 + i];
                const float4* wr = (const float4*)(vgoW_s + i*64 + q*16);
                #pragma unroll
                for (int jj=0;jj<4;jj++){
                    float4 w = wr[jj];
                    pg4[jj].x = fmaf(g, w.x, pg4[jj].x);
                    pg4[jj].y = fmaf(g, w.y, pg4[jj].y);
                    pg4[jj].z = fmaf(g, w.z, pg4[jj].z);
                    pg4[jj].w = fmaf(g, w.w, pg4[jj].w);
                }
            }
            float sumg = 0.f, sumg2 = 0.f;
            if (q == 0){
                sumg = sumv_s[24];
                #pragma unroll
                for (int i=0;i<24;i++) sumg = fmaf(gax[s*27+i], sumv_s[i], sumg);
            }
            if (q == 1){
                #pragma unroll
                for (int i=0;i<25;i++){
                    float ti = gram_s[i*28 + 24];
                    const float* gr = gram_s + i*28;
                    #pragma unroll
                    for (int jx=0;jx<24;jx++) ti = fmaf(gr[jx], gax[s*27+jx], ti);
                    float gi = (i<24) ? gax[s*27+i] : 1.f;
                    sumg2 = fmaf(gi, ti, sumg2);
                }
            }
            if (n0 + s < NS){
                float* dst = g_pg + ((size_t)b*NS + (n0+s))*68;
                float4* d4 = (float4*)(dst + q*16);
                #pragma unroll
                for (int jj=0;jj<4;jj++) d4[jj] = pg4[jj];
                if (q == 0) dst[64] = sumg;
                if (q == 1) dst[65] = sumg2;
            }
        }
    }

    gbar(2);

    // ===================== PHASE D: fused main (single-b, 32 warps/SM) ======
    {
        float* cst = smp;                 // 512
        float* rwT = smp + 512;           // 16 warps x 1024
        if (tid < 128) cst[tid] = Wnbr[tid];
        if (tid >= 128 && tid < 384) cst[tid] = g_cst[tid-128];
        if (tid >= 384 && tid < 448) cst[tid] = Wm2[tid-384];
        __syncthreads();
        const float* w0_s  = cst;
        const float* w1_s  = cst + 64;
        const float* w0W_s = cst + 128;
        const float* w1W_s = cst + 192;
        const float* gcol_s= cst + 256;
        const float* cadd_s= cst + 320;
        const float* wm2_s = cst + 384;
        float bm2v = bm2[0];
        float* myT = rwT + (tid>>5)*1024;

        for (;;){
            int n;
            if (lane == 0) n = (int)atomicAdd(&g_tkt[3], 1);
            n = __shfl_sync(FULLM, n, 0);
            if (n >= NS) break;

            int kj = 0; unsigned mkb = 0;
            if (lane < 16){ kj = knn[n*16 + lane]; mkb = g_mb[kj]; }
            unsigned mbn = g_mb[n];
            float a0 = g_a0[n], a1 = g_a1[n];
            float ql0 = g_ql[n*64 + lane], ql1 = g_ql[n*64 + 32 + lane];
            float rsp0[16], rsp1[16];
            #pragma unroll
            for (int k=0;k<16;k++){
                int j = __shfl_sync(FULLM, kj, k);
                rsp0[k] = g_sp[j*64 + lane];
                rsp1[k] = g_sp[j*64 + 32 + lane];
                myT[k*64 + lane]      = g_spW[j*64 + lane];
                myT[k*64 + 32 + lane] = g_spW[j*64 + 32 + lane];
            }
            float Sreg = 0.f;
            #pragma unroll
            for (int k0=0;k0<16;k0+=8){
                float p[8];
                #pragma unroll
                for (int u=0;u<8;u++) p[u] = fmaf(rsp0[k0+u], ql0, rsp1[k0+u]*ql1);
                wsumv<8>(p);
                #pragma unroll
                for (int u=0;u<8;u++) if (lane == k0+u) Sreg = p[u];
            }

            #pragma unroll 2
            for (int b=0;b<16;b++){
                const float* pg = g_pg + ((size_t)b*NS + n)*68;
                float Pg0  = pg[lane];
                float Pg1  = pg[32+lane];
                float sumg = pg[64];
                float sumg2= pg[65];

                float x0 = 0.f, x1 = 0.f, e = 0.f;
                if (lane < 16){
                    float2 xv = *(const float2*)(g_xq + kj*32 + b*2);
                    x0 = xv.x; x1 = xv.y;
                    float l = (Sreg + x0*a0 + x1*a1)*0.125f;
                    e = ((mkb >> b) & 1u) ? 1e-20f : __expf(l);
                }
                float red[3];
                red[0] = e; red[1] = e*x0; red[2] = e*x1;
                wsumv<3>(red);
                float inv = 1.f/red[0];
                float attn = e*inv;
                float alpha = red[1]*inv, beta = red[2]*inv;

                float L0 = alpha*w0_s[lane]      + beta*w1_s[lane];
                float L1 = alpha*w0_s[32+lane]   + beta*w1_s[32+lane];
                float P0 = alpha*w0W_s[lane]     + beta*w1W_s[lane];
                float P1 = alpha*w0W_s[32+lane]  + beta*w1W_s[32+lane];
                #pragma unroll
                for (int k=0;k<16;k++){
                    float ak = __shfl_sync(FULLM, attn, k);
                    L0 = fmaf(ak, rsp0[k], L0);
                    L1 = fmaf(ak, rsp1[k], L1);
                    P0 = fmaf(ak, myT[k*64 + lane],      P0);
                    P1 = fmaf(ak, myT[k*64 + 32 + lane], P1);
                }
                float rl[2];
                rl[0] = L0 + L1;
                rl[1] = L0*L0 + L1*L1;
                wsumv<2>(rl);

                float mean = (rl[0] + sumg)*(1.f/192.f);
                float var  = (rl[1] + sumg2)*(1.f/192.f) - mean*mean;
                float rstd = rsqrtf(var + 1e-5f);
                float h0 = fmaf(rstd, (P0+Pg0) - mean*gcol_s[lane],    cadd_s[lane]);
                float h1 = fmaf(rstd, (P1+Pg1) - mean*gcol_s[32+lane], cadd_s[32+lane]);
                float g0 = 0.5f*h0*(1.f + erff(h0*0.70710678118654752f));
                float g1 = 0.5f*h1*(1.f + erff(h1*0.70710678118654752f));
                float pr = wsum(fmaf(g0, wm2_s[lane], g1*wm2_s[32+lane]));
                if (lane == 0){
                    out[b*NS + n] = ((mbn >> b) & 1u) ? (pr + bm2v) : 0.f;
                }
            }
        }
    }
}

// ------------------------- launch -------------------------
extern "C" void kernel_launch(void* const* d_in, const int* in_sizes, int n_in,
                              void* d_out, int out_size){
    const float* xf    = (const float*)d_in[0];
    const float* latent= (const float*)d_in[1];
    const float* pos   = (const float*)d_in[2];
    const float* femb  = (const float*)d_in[3];
    const float* Wnbr  = (const float*)d_in[4];
    const float* bnbr  = (const float*)d_in[5];
    const float* Wql   = (const float*)d_in[6];
    const float* bql   = (const float*)d_in[7];
    const float* Wlat  = (const float*)d_in[8];
    const float* blat  = (const float*)d_in[9];
    const float* Wlf   = (const float*)d_in[10];
    const float* blf   = (const float*)d_in[11];
    const float* Wqg   = (const float*)d_in[12];
    const float* bqg   = (const float*)d_in[13];
    const float* Wk    = (const float*)d_in[14];
    const float* bk    = (const float*)d_in[15];
    const float* Wv    = (const float*)d_in[16];
    const float* bv    = (const float*)d_in[17];
    const float* Wgo   = (const float*)d_in[18];
    const float* bgo   = (const float*)d_in[19];
    const float* lng   = (const float*)d_in[20];
    const float* lnb   = (const float*)d_in[21];
    const float* Wm1   = (const float*)d_in[22];
    const float* bm1   = (const float*)d_in[23];
    const float* Wm2   = (const float*)d_in[24];
    const float* bm2   = (const float*)d_in[25];
    const int* mask    = (const int*)d_in[26];
    const int* knn     = (const int*)d_in[27];
    const int* fid     = (const int*)d_in[28];
    float* out = (float*)d_out;

    static int smem_sz = 23580*4;
    cudaFuncSetAttribute(kAll, cudaFuncAttributeMaxDynamicSharedMemorySize, smem_sz);

    kAll<<<NBLK, 512, smem_sz>>>(
        xf, latent, pos, femb, Wnbr, bnbr, Wql, bql, Wlat, blat, Wlf, blf,
        Wqg, bqg, Wk, bk, Wv, bv, Wgo, bgo, lng, lnb, Wm1, bm1, Wm2, bm2,
        mask, knn, fid, out);
}

// round 16
// speedup vs baseline: 1.1996x; 1.1274x over previous
#include <cuda_runtime.h>
#include <math.h>
#include <math_constants.h>

#define NS 4760
#define NB 16
#define NT 6
#define NBLK 148
#define FULLM 0xffffffffu

// ------------------------- device scratch -------------------------
__device__ float g_q  [NS*128];
__device__ float g_Wpack[128*328 + 64];
__device__ float g_bpack[328];
__device__ float g_ql [NS*64];
__device__ float g_sp [NS*64];
__device__ float g_spW[NS*64];
__device__ float g_qg [NS*128];
__device__ float g_a0 [NS];
__device__ float g_a1 [NS];
__device__ float g_kg [NB*NT*128];
__device__ float g_vgo [NB*25*128];
__device__ float g_vgoW[NB*25*64];
__device__ float g_sumv[NB*25];
__device__ float g_gram[NB*25*25];
__device__ float g_pg  [(size_t)NB*NS*68];   // [b][n][68]
__device__ float g_cst [256];
__device__ float g_xq  [NS*32];              // [n][b][2]
__device__ unsigned g_mb[NS];
__device__ unsigned g_tkt[4];
__device__ unsigned g_barcnt[4];

__device__ __forceinline__ float wsum(float v){
    #pragma unroll
    for (int o=16;o;o>>=1) v += __shfl_xor_sync(FULLM, v, o);
    return v;
}
template<int N>
__device__ __forceinline__ void wsumv(float* v){
    #pragma unroll
    for (int o=16;o;o>>=1){
        #pragma unroll
        for (int i=0;i<N;i++) v[i] += __shfl_xor_sync(FULLM, v[i], o);
    }
}

__device__ __forceinline__ void gbar(int i){
    __syncthreads();
    if (threadIdx.x == 0){
        __threadfence();
        unsigned old = atomicAdd(&g_barcnt[i], 1);
        if (old == NBLK-1){
            atomicExch(&g_barcnt[i], 0);
        } else {
            while (atomicAdd(&g_barcnt[i], 0) != 0) { }
        }
        __threadfence();
    }
    __syncthreads();
}

// ------------------------- the one kernel -------------------------
__global__ void __launch_bounds__(512,1) kAll(
    const float* __restrict__ xf,    const float* __restrict__ latent,
    const float* __restrict__ pos,   const float* __restrict__ femb,
    const float* __restrict__ Wnbr,  const float* __restrict__ bnbr,
    const float* __restrict__ Wql,   const float* __restrict__ bql,
    const float* __restrict__ Wlat,  const float* __restrict__ blat,
    const float* __restrict__ Wlf,   const float* __restrict__ blf,
    const float* __restrict__ Wqg,   const float* __restrict__ bqg,
    const float* __restrict__ Wk,    const float* __restrict__ bk,
    const float* __restrict__ Wv,    const float* __restrict__ bv,
    const float* __restrict__ Wgo,   const float* __restrict__ bgo,
    const float* __restrict__ lng,   const float* __restrict__ lnb,
    const float* __restrict__ Wm1,   const float* __restrict__ bm1,
    const float* __restrict__ Wm2,   const float* __restrict__ bm2,
    const int*   __restrict__ mask,  const int* __restrict__ knn,
    const int*   __restrict__ fid,   float* __restrict__ out)
{
    extern __shared__ float smp[];
    __shared__ int s_t;
    int tid = threadIdx.x;
    int bid = blockIdx.x;
    int lane = tid & 31;

    // ===================== PHASE A =====================
    if (bid < 96){
        float* lat_s = smp;           // 1056
        float* part  = smp + 1056;    // 512
        float* kv_s  = smp + 1568;    // 128
        float* vg_s  = smp + 1696;    // 128
        int t = bid % NT, b = bid / NT;
        for (int e=tid;e<1024;e+=512) lat_s[e] = latent[((size_t)b*NT+t)*1024 + e];
        if (tid < 32) lat_s[1024+tid] = femb[t*32+tid];
        __syncthreads();
        int j = tid & 127, q = tid >> 7;
        {
            float ac0 = (q==0) ? (blat[j]+blf[j]) : 0.f;
            float ac1 = 0.f, ac2 = 0.f, ac3 = 0.f;
            int i0 = q*256;
            #pragma unroll 4
            for (int i=i0;i<i0+256;i+=4){
                ac0 = fmaf(lat_s[i],   Wlat[(i  )*128+j], ac0);
                ac1 = fmaf(lat_s[i+1], Wlat[(i+1)*128+j], ac1);
                ac2 = fmaf(lat_s[i+2], Wlat[(i+2)*128+j], ac2);
                ac3 = fmaf(lat_s[i+3], Wlat[(i+3)*128+j], ac3);
            }
            float acc = (ac0+ac1)+(ac2+ac3);
            if (q==3){
                for (int f=0;f<32;f++) acc = fmaf(lat_s[1024+f], Wlf[f*128+j], acc);
            }
            part[q*128+j] = acc;
        }
        __syncthreads();
        if (tid < 128) kv_s[tid] = part[tid] + part[128+tid] + part[256+tid] + part[384+tid];
        __syncthreads();
        {
            const float* W = (q < 2) ? Wk : Wv;
            float b0 = 0.f, b1 = 0.f, b2 = 0.f, b3 = 0.f;
            int i0 = (q & 1)*64;
            #pragma unroll 4
            for (int i=i0;i<i0+64;i+=4){
                b0 = fmaf(kv_s[i],   W[(i  )*128+j], b0);
                b1 = fmaf(kv_s[i+1], W[(i+1)*128+j], b1);
                b2 = fmaf(kv_s[i+2], W[(i+2)*128+j], b2);
                b3 = fmaf(kv_s[i+3], W[(i+3)*128+j], b3);
            }
            part[q*128+j] = (b0+b1)+(b2+b3);
        }
        __syncthreads();
        if (tid < 128) g_kg[(b*NT+t)*128 + tid] = part[tid] + part[128+tid] + bk[tid];
        else if (tid < 256){ int jj = tid-128; vg_s[jj] = part[256+jj] + part[384+jj] + bv[jj]; }
        __syncthreads();
        {
            int h = tid >> 7, j2 = tid & 127;
            float a = 0.f;
            #pragma unroll
            for (int d=0;d<32;d++) a = fmaf(vg_s[h*32+d], Wgo[(h*32+d)*128+j2], a);
            g_vgo[((size_t)b*25 + t*4 + h)*128 + j2] = a;
        }
        if (t==0 && tid<128) g_vgo[((size_t)b*25 + 24)*128 + tid] = bgo[tid];
    } else if (bid == 96){
        if (tid == 0){ g_tkt[0]=0; g_tkt[1]=0; g_tkt[2]=0; g_tkt[3]=0; }
        float* W1t = smp;
        for (int e=tid;e<4096;e+=512) W1t[e] = lng[e>>6]*Wm1[e];
        __syncthreads();
        for (int e=tid;e<8192;e+=512){
            int k=e>>6, j=e&63;
            g_Wpack[k*328 + j]      = Wql[e];
            g_Wpack[k*328 + 64 + j] = Wnbr[128+e];
        }
        for (int e=tid;e<16384;e+=512){
            int k=e>>7, j=e&127;
            g_Wpack[k*328 + 128 + j] = Wqg[e];
        }
        for (int e=tid;e<8192;e+=512){
            int c=e>>6, j=e&63;
            float a = 0.f;
            #pragma unroll 4
            for (int i=0;i<64;i++) a = fmaf(Wnbr[128 + c*64 + i], W1t[i*64+j], a);
            g_Wpack[c*328 + 256 + j] = a;
        }
        if (tid < 256){
            int k = tid & 127, which = tid >> 7;
            float a = 0.f;
            for (int i=0;i<64;i++) a = fmaf(Wql[k*64+i], Wnbr[which*64 + i], a);
            g_Wpack[k*328 + 320 + which] = a;
        }
        if (tid < 128){
            for (int c=322;c<328;c++) g_Wpack[tid*328+c] = 0.f;
        }
        if (tid < 64){
            g_bpack[tid]      = bql[tid];
            g_bpack[64+tid]   = bnbr[tid];
            float bf = 0.f;
            for (int i=0;i<64;i++) bf = fmaf(bnbr[i], W1t[i*64+tid], bf);
            g_bpack[256+tid] = bf;
        }
        if (tid < 128) g_bpack[128+tid] = bqg[tid];
        if (tid == 0){
            float a0=0.f, a1=0.f;
            for (int i=0;i<64;i++){ a0 = fmaf(bql[i], Wnbr[i], a0); a1 = fmaf(bql[i], Wnbr[64+i], a1); }
            g_bpack[320] = a0; g_bpack[321] = a1;
        }
        if (tid < 64){
            int j = tid;
            float w0W=0.f, w1W=0.f, gcol=0.f, cadd=0.f;
            for (int i=0;i<192;i++){
                float w = Wm1[i*64+j];
                gcol += lng[i]*w;
                cadd += lnb[i]*w;
            }
            for (int i=0;i<64;i++){
                float w = lng[i]*Wm1[i*64+j];
                w0W += Wnbr[i]     * w;
                w1W += Wnbr[64+i]  * w;
            }
            g_cst[j]      = w0W;
            g_cst[64+j]   = w1W;
            g_cst[128+j]  = gcol;
            g_cst[192+j]  = cadd + bm1[j];
        }
    } else if (bid < 116){
        int n0 = (bid - 97) * 256;
        for (int e=tid;e<256*128;e+=512){
            int s = e>>7, k = e&127, n = n0 + s;
            if (n >= NS) break;
            g_q[n*128 + k] = (k<96) ? pos[n*96+k] : femb[fid[n]*32 + (k-96)];
        }
    } else {
        int tb = bid - 116;
        int nlo = tb*149, nhi = nlo+149; if (nhi > NS) nhi = NS;
        for (int n = nlo + tid; n < nhi; n += 512){
            unsigned mb = 0;
            #pragma unroll
            for (int b=0;b<16;b+=2){
                float2 xa = *(const float2*)(xf + ((size_t)b*NS + n)*2);
                float2 xb = *(const float2*)(xf + ((size_t)(b+1)*NS + n)*2);
                float4 o; o.x=xa.x; o.y=xa.y; o.z=xb.x; o.w=xb.y;
                *(float4*)(g_xq + n*32 + b*2) = o;
                if (mask[b*NS+n])     mb |= (1u<<b);
                if (mask[(b+1)*NS+n]) mb |= (1u<<(b+1));
            }
            g_mb[n] = mb;
        }
    }

    gbar(0);

    // ===================== PHASE B: GEMM tiles (k-split) + folds ===========
    {
        float* AT = smp;            // 8704
        float* Ws = smp + 8704;     // 8192
        float* Rb = smp + 16896;    // 256*17 = 4352
        for (;;){
            __syncthreads();
            if (tid == 0) s_t = (int)atomicAdd(&g_tkt[0], 1);
            __syncthreads();
            int tt = s_t;
            if (tt >= 450) break;
            int n0 = (tt/6)*64, c0 = (tt%6)*64;
            for (int e=tid*4;e<8192;e+=2048){
                int s = e>>7, k = e&127, n = n0+s;
                float4 v;
                if (n < NS) v = *(const float4*)(g_q + n*128 + k);
                else { v.x=0.f; v.y=0.f; v.z=0.f; v.w=0.f; }
                AT[(k  )*68 + s] = v.x;
                AT[(k+1)*68 + s] = v.y;
                AT[(k+2)*68 + s] = v.z;
                AT[(k+3)*68 + s] = v.w;
            }
            for (int e=tid*4;e<8192;e+=2048){
                int k = e>>6, cc = e&63;
                *(float4*)(Ws + e) = *(const float4*)(g_Wpack + k*328 + c0 + cc);
            }
            __syncthreads();

            int cg = tid & 15, sgr = (tid >> 4) & 15, kh = tid >> 8;
            int rid = tid & 255;
            const float4* Wb = (const float4*)Ws + cg;
            float acc[4][4];
            #pragma unroll
            for (int s=0;s<4;s++){ acc[s][0]=0.f; acc[s][1]=0.f; acc[s][2]=0.f; acc[s][3]=0.f; }
            int kbeg = kh*64;
            #pragma unroll 4
            for (int k=kbeg;k<kbeg+64;k++){
                float4 w = Wb[k*16];
                float4 a = ((const float4*)(AT + k*68))[sgr];
                float av[4] = {a.x, a.y, a.z, a.w};
                #pragma unroll
                for (int s=0;s<4;s++){
                    acc[s][0] = fmaf(av[s], w.x, acc[s][0]);
                    acc[s][1] = fmaf(av[s], w.y, acc[s][1]);
                    acc[s][2] = fmaf(av[s], w.z, acc[s][2]);
                    acc[s][3] = fmaf(av[s], w.w, acc[s][3]);
                }
            }
            if (kh == 1){
                float* r = Rb + rid*17;
                #pragma unroll
                for (int s=0;s<4;s++){
                    r[s*4+0] = acc[s][0]; r[s*4+1] = acc[s][1];
                    r[s*4+2] = acc[s][2]; r[s*4+3] = acc[s][3];
                }
            }
            __syncthreads();
            if (kh == 0){
                const float* r = Rb + rid*17;
                #pragma unroll
                for (int s=0;s<4;s++){
                    int n = n0 + sgr*4 + s;
                    if (n >= NS) continue;
                    #pragma unroll
                    for (int u=0;u<4;u++){
                        int c = c0 + cg*4 + u;
                        if (c >= 322) continue;
                        float v = acc[s][u] + r[s*4+u] + g_bpack[c];
                        if (c < 64)        g_ql [n*64 + c]        = v;
                        else if (c < 128)  g_sp [n*64 + (c-64)]   = v;
                        else if (c < 256)  g_qg [n*128 + (c-128)] = v;
                        else if (c < 320)  g_spW[n*64 + (c-256)]  = v;
                        else if (c == 320) g_a0[n] = v;
                        else               g_a1[n] = v;
                    }
                }
            }
        }
        __syncthreads();
        float* w1bT = smp;   // 8448
        for (int e=tid;e<8192;e+=512){ int c=e>>6, j=e&63; w1bT[j*132+c] = lng[64+c]*Wm1[4096+e]; }
        __syncthreads();
        int c4 = lane*4;
        for (;;){
            int base;
            if (lane == 0) base = (int)atomicAdd(&g_tkt[1], 8);
            base = __shfl_sync(FULLM, base, 0);
            if (base >= 36000) break;
            #pragma unroll
            for (int k8=0;k8<8;k8++){
                int task = base + k8;
                if (task >= 36000) break;
                int b = task/2250, tt2 = task - b*2250;
                if (tt2 < 1600){
                    int i = tt2 >> 6, j = tt2 & 63;
                    float4 a = *(const float4*)(g_vgo + ((size_t)b*25+i)*128 + c4);
                    float4 w = *(const float4*)(w1bT + j*132 + c4);
                    float v = a.x*w.x + a.y*w.y + a.z*w.z + a.w*w.w;
                    v = wsum(v);
                    if (lane==0) g_vgoW[(b*25+i)*64 + j] = v;
                } else if (tt2 < 2225){
                    int p = tt2 - 1600, i1 = p/25, i2 = p - i1*25;
                    float4 a = *(const float4*)(g_vgo + ((size_t)b*25+i1)*128 + c4);
                    float4 c = *(const float4*)(g_vgo + ((size_t)b*25+i2)*128 + c4);
                    float v = a.x*c.x + a.y*c.y + a.z*c.z + a.w*c.w;
                    v = wsum(v);
                    if (lane==0) g_gram[b*625 + p] = v;
                } else {
                    int i = tt2 - 2225;
                    float4 a = *(const float4*)(g_vgo + ((size_t)b*25+i)*128 + c4);
                    float v = a.x + a.y + a.z + a.w;
                    v = wsum(v);
                    if (lane==0) g_sumv[b*25 + i] = v;
                }
            }
        }
    }

    gbar(1);

    // ===================== PHASE C: softmax + Pg (2 b per qs staging) ======
    {
        float* qs     = smp;              // 17024
        float* Ks     = smp + 17024;      // 768
        float* vgoW_s = smp + 17792;      // 1600
        float* gram_s = smp + 19392;      // 700
        float* sumv_s = smp + 20092;      // 32
        float* gax    = smp + 20124;      // 3456
        const float scale = 0.17677669529663687f;
        for (;;){
            __syncthreads();
            if (tid == 0) s_t = (int)atomicAdd(&g_tkt[2], 1);
            __syncthreads();
            int tt = s_t;
            if (tt >= 304) break;
            int bp = tt & 7, n0 = (tt >> 3)*128;

            for (int e=tid;e<16384;e+=512){
                int s=e>>7, k=e&127;
                int nr = (n0+s < NS) ? (n0+s) : (NS-1);
                qs[s*133+k] = g_qg[nr*128 + k];
            }

            #pragma unroll
            for (int bi=0;bi<2;bi++){
                int b = bp*2 + bi;
                for (int e=tid;e<768;e+=512){
                    int r=e>>5, k=e&31, h=r/6, t2=r%6;
                    Ks[e] = g_kg[(b*NT+t2)*128 + h*32 + k];
                }
                for (int e=tid;e<1600;e+=512) vgoW_s[e] = g_vgoW[b*1600 + e];
                for (int e=tid;e<625;e+=512){ int i=e/25, jj=e-i*25; gram_s[i*28+jj] = g_gram[b*625 + e]; }
                if (tid < 25) sumv_s[tid] = g_sumv[b*25 + tid];
                __syncthreads();

                int s = tid & 127, q = tid >> 7;
                {
                    float qv[32];
                    #pragma unroll
                    for (int k=0;k<32;k++) qv[k] = qs[s*133 + q*32 + k];
                    float lg[6];
                    #pragma unroll
                    for (int t2=0;t2<6;t2++){
                        const float* kr = Ks + (q*6+t2)*32;
                        float a = 0.f;
                        #pragma unroll
                        for (int k=0;k<32;k++) a = fmaf(qv[k], kr[k], a);
                        lg[t2] = a;
                    }
                    float m = lg[0];
                    #pragma unroll
                    for (int t2=1;t2<6;t2++) m = fmaxf(m, lg[t2]);
                    float den = 0.f, ex[6];
                    #pragma unroll
                    for (int t2=0;t2<6;t2++){ ex[t2] = __expf((lg[t2]-m)*scale); den += ex[t2]; }
                    float inv = 1.f/den;
                    #pragma unroll
                    for (int t2=0;t2<6;t2++) gax[s*27 + t2*4 + q] = ex[t2]*inv;
                }
                __syncthreads();

                float ga[25];
                #pragma unroll
                for (int i=0;i<24;i++) ga[i] = gax[s*27 + i];
                ga[24] = 1.f;

                float4 pg4[4];
                {
                    const float4* w24 = (const float4*)(vgoW_s + 24*64 + q*16);
                    #pragma unroll
                    for (int jj=0;jj<4;jj++) pg4[jj] = w24[jj];
                }
                #pragma unroll
                for (int i=0;i<24;i++){
                    float g = ga[i];
                    const float4* wr = (const float4*)(vgoW_s + i*64 + q*16);
                    #pragma unroll
                    for (int jj=0;jj<4;jj++){
                        float4 w = wr[jj];
                        pg4[jj].x = fmaf(g, w.x, pg4[jj].x);
                        pg4[jj].y = fmaf(g, w.y, pg4[jj].y);
                        pg4[jj].z = fmaf(g, w.z, pg4[jj].z);
                        pg4[jj].w = fmaf(g, w.w, pg4[jj].w);
                    }
                }
                float sumg = 0.f, sumg2 = 0.f;
                if (q == 0){
                    sumg = sumv_s[24];
                    #pragma unroll
                    for (int i=0;i<24;i++) sumg = fmaf(ga[i], sumv_s[i], sumg);
                }
                if (q == 1){
                    #pragma unroll
                    for (int i=0;i<25;i++){
                        float ti = gram_s[i*28 + 24];
                        #pragma unroll
                        for (int j4=0;j4<6;j4++){
                            float4 gv = *(const float4*)(gram_s + i*28 + j4*4);
                            ti = fmaf(gv.x, ga[j4*4+0], ti);
                            ti = fmaf(gv.y, ga[j4*4+1], ti);
                            ti = fmaf(gv.z, ga[j4*4+2], ti);
                            ti = fmaf(gv.w, ga[j4*4+3], ti);
                        }
                        sumg2 = fmaf(ga[i], ti, sumg2);
                    }
                }
                if (n0 + s < NS){
                    float* dst = g_pg + ((size_t)b*NS + (n0+s))*68;
                    float4* d4 = (float4*)(dst + q*16);
                    #pragma unroll
                    for (int jj=0;jj<4;jj++) d4[jj] = pg4[jj];
                    if (q == 0) dst[64] = sumg;
                    if (q == 1) dst[65] = sumg2;
                }
                __syncthreads();
            }
        }
    }

    gbar(2);

    // ===================== PHASE D: fused main (R9 structure) ==============
    {
        float* cst = smp;                 // 512
        float* rwT = smp + 512;           // 16 warps x 1024
        if (tid < 128) cst[tid] = Wnbr[tid];
        if (tid >= 128 && tid < 384) cst[tid] = g_cst[tid-128];
        if (tid >= 384 && tid < 448) cst[tid] = Wm2[tid-384];
        __syncthreads();
        const float* w0_s  = cst;
        const float* w1_s  = cst + 64;
        const float* w0W_s = cst + 128;
        const float* w1W_s = cst + 192;
        const float* gcol_s= cst + 256;
        const float* cadd_s= cst + 320;
        const float* wm2_s = cst + 384;
        float bm2v = bm2[0];
        float* myT = rwT + (tid>>5)*1024;

        for (;;){
            int n;
            if (lane == 0) n = (int)atomicAdd(&g_tkt[3], 1);
            n = __shfl_sync(FULLM, n, 0);
            if (n >= NS) break;

            int kj = 0; unsigned mkb = 0;
            if (lane < 16){ kj = knn[n*16 + lane]; mkb = g_mb[kj]; }
            unsigned mbn = g_mb[n];
            float a0 = g_a0[n], a1 = g_a1[n];
            float ql0 = g_ql[n*64 + lane], ql1 = g_ql[n*64 + 32 + lane];
            float rsp0[16], rsp1[16];
            #pragma unroll
            for (int k=0;k<16;k++){
                int j = __shfl_sync(FULLM, kj, k);
                rsp0[k] = g_sp[j*64 + lane];
                rsp1[k] = g_sp[j*64 + 32 + lane];
                myT[k*64 + lane]      = g_spW[j*64 + lane];
                myT[k*64 + 32 + lane] = g_spW[j*64 + 32 + lane];
            }
            float Sreg = 0.f;
            #pragma unroll
            for (int k0=0;k0<16;k0+=8){
                float p[8];
                #pragma unroll
                for (int u=0;u<8;u++) p[u] = fmaf(rsp0[k0+u], ql0, rsp1[k0+u]*ql1);
                wsumv<8>(p);
                #pragma unroll
                for (int u=0;u<8;u++) if (lane == k0+u) Sreg = p[u];
            }

            #pragma unroll
            for (int hb=0;hb<2;hb++){
                float4 xq4[4];
                #pragma unroll
                for (int u=0;u<4;u++){ xq4[u].x=0.f; xq4[u].y=0.f; xq4[u].z=0.f; xq4[u].w=0.f; }
                if (lane < 16){
                    const float4* px = (const float4*)(g_xq + kj*32 + hb*16);
                    #pragma unroll
                    for (int u=0;u<4;u++) xq4[u] = px[u];
                }
                #pragma unroll
                for (int pg2=0;pg2<2;pg2++){
                    float pr4[4];
                    #pragma unroll
                    for (int bp2=0;bp2<2;bp2++){
                        int bp = pg2*2 + bp2;
                        int b0 = hb*8 + bp*2, b1 = b0 + 1;
                        const float* pgA = g_pg + ((size_t)b0*NS + n)*68;
                        const float* pgB = g_pg + ((size_t)b1*NS + n)*68;
                        float PgA0 = pgA[lane], PgA1 = pgA[32+lane];
                        float sgA  = pgA[64],   sg2A = pgA[65];
                        float PgB0 = pgB[lane], PgB1 = pgB[32+lane];
                        float sgB  = pgB[64],   sg2B = pgB[65];

                        float4 xv = xq4[bp];
                        float x00 = xv.x, x01 = xv.y, x10 = xv.z, x11 = xv.w;
                        float e0 = 0.f, e1 = 0.f;
                        if (lane < 16){
                            float l0 = (Sreg + x00*a0 + x01*a1)*0.125f;
                            float l1 = (Sreg + x10*a0 + x11*a1)*0.125f;
                            e0 = ((mkb >> b0) & 1u) ? 1e-20f : __expf(l0);
                            e1 = ((mkb >> b1) & 1u) ? 1e-20f : __expf(l1);
                        }
                        float red[6];
                        red[0] = e0; red[1] = e0*x00; red[2] = e0*x01;
                        red[3] = e1; red[4] = e1*x10; red[5] = e1*x11;
                        wsumv<6>(red);
                        float inv0 = 1.f/red[0], inv1 = 1.f/red[3];
                        float at0 = e0*inv0, at1 = e1*inv1;
                        float al0 = red[1]*inv0, be0 = red[2]*inv0;
                        float al1 = red[4]*inv1, be1 = red[5]*inv1;

                        float L00 = al0*w0_s[lane]      + be0*w1_s[lane];
                        float L01 = al0*w0_s[32+lane]   + be0*w1_s[32+lane];
                        float P00 = al0*w0W_s[lane]     + be0*w1W_s[lane];
                        float P01 = al0*w0W_s[32+lane]  + be0*w1W_s[32+lane];
                        float L10 = al1*w0_s[lane]      + be1*w1_s[lane];
                        float L11 = al1*w0_s[32+lane]   + be1*w1_s[32+lane];
                        float P10 = al1*w0W_s[lane]     + be1*w1W_s[lane];
                        float P11 = al1*w0W_s[32+lane]  + be1*w1W_s[32+lane];
                        #pragma unroll
                        for (int k=0;k<16;k++){
                            float ak0 = __shfl_sync(FULLM, at0, k);
                            float ak1 = __shfl_sync(FULLM, at1, k);
                            float w0v = myT[k*64 + lane];
                            float w1v = myT[k*64 + 32 + lane];
                            L00 = fmaf(ak0, rsp0[k], L00);
                            L01 = fmaf(ak0, rsp1[k], L01);
                            L10 = fmaf(ak1, rsp0[k], L10);
                            L11 = fmaf(ak1, rsp1[k], L11);
                            P00 = fmaf(ak0, w0v, P00);
                            P01 = fmaf(ak0, w1v, P01);
                            P10 = fmaf(ak1, w0v, P10);
                            P11 = fmaf(ak1, w1v, P11);
                        }
                        float rl[4];
                        rl[0] = L00 + L01;
                        rl[1] = L00*L00 + L01*L01;
                        rl[2] = L10 + L11;
                        rl[3] = L10*L10 + L11*L11;
                        wsumv<4>(rl);

                        float mean0 = (rl[0] + sgA)*(1.f/192.f);
                        float var0  = (rl[1] + sg2A)*(1.f/192.f) - mean0*mean0;
                        float rstd0 = rsqrtf(var0 + 1e-5f);
                        float h00 = fmaf(rstd0, (P00+PgA0) - mean0*gcol_s[lane],    cadd_s[lane]);
                        float h01 = fmaf(rstd0, (P01+PgA1) - mean0*gcol_s[32+lane], cadd_s[32+lane]);
                        float g00 = 0.5f*h00*(1.f + erff(h00*0.70710678118654752f));
                        float g01 = 0.5f*h01*(1.f + erff(h01*0.70710678118654752f));

                        float mean1 = (rl[2] + sgB)*(1.f/192.f);
                        float var1  = (rl[3] + sg2B)*(1.f/192.f) - mean1*mean1;
                        float rstd1 = rsqrtf(var1 + 1e-5f);
                        float h10 = fmaf(rstd1, (P10+PgB0) - mean1*gcol_s[lane],    cadd_s[lane]);
                        float h11 = fmaf(rstd1, (P11+PgB1) - mean1*gcol_s[32+lane], cadd_s[32+lane]);
                        float g10 = 0.5f*h10*(1.f + erff(h10*0.70710678118654752f));
                        float g11 = 0.5f*h11*(1.f + erff(h11*0.70710678118654752f));

                        pr4[bp2*2+0] = fmaf(g00, wm2_s[lane], g01*wm2_s[32+lane]);
                        pr4[bp2*2+1] = fmaf(g10, wm2_s[lane], g11*wm2_s[32+lane]);
                    }
                    wsumv<4>(pr4);
                    if (lane == 0){
                        int bb = hb*8 + pg2*4;
                        out[(bb+0)*NS + n] = ((mbn >> (bb+0)) & 1u) ? (pr4[0] + bm2v) : 0.f;
                        out[(bb+1)*NS + n] = ((mbn >> (bb+1)) & 1u) ? (pr4[1] + bm2v) : 0.f;
                        out[(bb+2)*NS + n] = ((mbn >> (bb+2)) & 1u) ? (pr4[2] + bm2v) : 0.f;
                        out[(bb+3)*NS + n] = ((mbn >> (bb+3)) & 1u) ? (pr4[3] + bm2v) : 0.f;
                    }
                }
            }
        }
    }
}

// ------------------------- launch -------------------------
extern "C" void kernel_launch(void* const* d_in, const int* in_sizes, int n_in,
                              void* d_out, int out_size){
    const float* xf    = (const float*)d_in[0];
    const float* latent= (const float*)d_in[1];
    const float* pos   = (const float*)d_in[2];
    const float* femb  = (const float*)d_in[3];
    const float* Wnbr  = (const float*)d_in[4];
    const float* bnbr  = (const float*)d_in[5];
    const float* Wql   = (const float*)d_in[6];
    const float* bql   = (const float*)d_in[7];
    const float* Wlat  = (const float*)d_in[8];
    const float* blat  = (const float*)d_in[9];
    const float* Wlf   = (const float*)d_in[10];
    const float* blf   = (const float*)d_in[11];
    const float* Wqg   = (const float*)d_in[12];
    const float* bqg   = (const float*)d_in[13];
    const float* Wk    = (const float*)d_in[14];
    const float* bk    = (const float*)d_in[15];
    const float* Wv    = (const float*)d_in[16];
    const float* bv    = (const float*)d_in[17];
    const float* Wgo   = (const float*)d_in[18];
    const float* bgo   = (const float*)d_in[19];
    const float* lng   = (const float*)d_in[20];
    const float* lnb   = (const float*)d_in[21];
    const float* Wm1   = (const float*)d_in[22];
    const float* bm1   = (const float*)d_in[23];
    const float* Wm2   = (const float*)d_in[24];
    const float* bm2   = (const float*)d_in[25];
    const int* mask    = (const int*)d_in[26];
    const int* knn     = (const int*)d_in[27];
    const int* fid     = (const int*)d_in[28];
    float* out = (float*)d_out;

    static int smem_sz = 23580*4;
    cudaFuncSetAttribute(kAll, cudaFuncAttributeMaxDynamicSharedMemorySize, smem_sz);

    kAll<<<NBLK, 512, smem_sz>>>(
        xf, latent, pos, femb, Wnbr, bnbr, Wql, bql, Wlat, blat, Wlf, blf,
        Wqg, bqg, Wk, bk, Wv, bv, Wgo, bgo, lng, lnb, Wm1, bm1, Wm2, bm2,
        mask, knn, fid, out);
}

// round 17
// speedup vs baseline: 1.2618x; 1.0518x over previous
#include <cuda_runtime.h>
#include <math.h>
#include <math_constants.h>

#define NS 4760
#define NB 16
#define NT 6
#define NBLK 148
#define FULLM 0xffffffffu

// ------------------------- device scratch -------------------------
__device__ float g_q  [NS*128];
__device__ float g_Wpack[128*328 + 64];
__device__ float g_bpack[328];
__device__ float g_ql [NS*64];
__device__ float g_sp [NS*64];
__device__ float g_spW[NS*64];
__device__ float g_qg [NS*128];
__device__ float g_a0 [NS];
__device__ float g_a1 [NS];
__device__ float g_kg [NB*NT*128];
__device__ float g_vgo [NB*25*128];
__device__ float g_vgoW[NB*25*64];
__device__ float g_sumv[NB*25];
__device__ float g_gram[NB*25*25];
__device__ float g_pg  [(size_t)NB*NS*68];   // [b][n][68]
__device__ float g_cst [256];
__device__ float g_xq  [NS*32];              // [n][b][2]
__device__ unsigned g_mb[NS];
__device__ unsigned g_tkt[4];
__device__ unsigned g_barcnt[4];

__device__ __forceinline__ float wsum(float v){
    #pragma unroll
    for (int o=16;o;o>>=1) v += __shfl_xor_sync(FULLM, v, o);
    return v;
}
template<int N>
__device__ __forceinline__ void wsumv(float* v){
    #pragma unroll
    for (int o=16;o;o>>=1){
        #pragma unroll
        for (int i=0;i<N;i++) v[i] += __shfl_xor_sync(FULLM, v[i], o);
    }
}

__device__ __forceinline__ void gbar(int i){
    __syncthreads();
    if (threadIdx.x == 0){
        __threadfence();
        unsigned old = atomicAdd(&g_barcnt[i], 1);
        if (old == NBLK-1){
            atomicExch(&g_barcnt[i], 0);
        } else {
            while (atomicAdd(&g_barcnt[i], 0) != 0) { }
        }
        __threadfence();
    }
    __syncthreads();
}

// ------------------------- kAll: phases A, B, C -------------------------
__global__ void __launch_bounds__(512,1) kAll(
    const float* __restrict__ xf,    const float* __restrict__ latent,
    const float* __restrict__ pos,   const float* __restrict__ femb,
    const float* __restrict__ Wnbr,  const float* __restrict__ bnbr,
    const float* __restrict__ Wql,   const float* __restrict__ bql,
    const float* __restrict__ Wlat,  const float* __restrict__ blat,
    const float* __restrict__ Wlf,   const float* __restrict__ blf,
    const float* __restrict__ Wqg,   const float* __restrict__ bqg,
    const float* __restrict__ Wk,    const float* __restrict__ bk,
    const float* __restrict__ Wv,    const float* __restrict__ bv,
    const float* __restrict__ Wgo,   const float* __restrict__ bgo,
    const float* __restrict__ lng,   const float* __restrict__ lnb,
    const float* __restrict__ Wm1,   const float* __restrict__ bm1,
    const int*   __restrict__ mask,  const int* __restrict__ fid)
{
    extern __shared__ float smp[];
    __shared__ int s_t;
    int tid = threadIdx.x;
    int bid = blockIdx.x;
    int lane = tid & 31;

    // ===================== PHASE A =====================
    if (bid < 96){
        float* lat_s = smp;           // 1056
        float* part  = smp + 1056;    // 512
        float* kv_s  = smp + 1568;    // 128
        float* vg_s  = smp + 1696;    // 128
        int t = bid % NT, b = bid / NT;
        for (int e=tid;e<1024;e+=512) lat_s[e] = latent[((size_t)b*NT+t)*1024 + e];
        if (tid < 32) lat_s[1024+tid] = femb[t*32+tid];
        __syncthreads();
        int j = tid & 127, q = tid >> 7;
        {
            float ac0 = (q==0) ? (blat[j]+blf[j]) : 0.f;
            float ac1 = 0.f, ac2 = 0.f, ac3 = 0.f;
            int i0 = q*256;
            #pragma unroll 4
            for (int i=i0;i<i0+256;i+=4){
                ac0 = fmaf(lat_s[i],   Wlat[(i  )*128+j], ac0);
                ac1 = fmaf(lat_s[i+1], Wlat[(i+1)*128+j], ac1);
                ac2 = fmaf(lat_s[i+2], Wlat[(i+2)*128+j], ac2);
                ac3 = fmaf(lat_s[i+3], Wlat[(i+3)*128+j], ac3);
            }
            float acc = (ac0+ac1)+(ac2+ac3);
            if (q==3){
                for (int f=0;f<32;f++) acc = fmaf(lat_s[1024+f], Wlf[f*128+j], acc);
            }
            part[q*128+j] = acc;
        }
        __syncthreads();
        if (tid < 128) kv_s[tid] = part[tid] + part[128+tid] + part[256+tid] + part[384+tid];
        __syncthreads();
        {
            const float* W = (q < 2) ? Wk : Wv;
            float b0 = 0.f, b1 = 0.f, b2 = 0.f, b3 = 0.f;
            int i0 = (q & 1)*64;
            #pragma unroll 4
            for (int i=i0;i<i0+64;i+=4){
                b0 = fmaf(kv_s[i],   W[(i  )*128+j], b0);
                b1 = fmaf(kv_s[i+1], W[(i+1)*128+j], b1);
                b2 = fmaf(kv_s[i+2], W[(i+2)*128+j], b2);
                b3 = fmaf(kv_s[i+3], W[(i+3)*128+j], b3);
            }
            part[q*128+j] = (b0+b1)+(b2+b3);
        }
        __syncthreads();
        if (tid < 128) g_kg[(b*NT+t)*128 + tid] = part[tid] + part[128+tid] + bk[tid];
        else if (tid < 256){ int jj = tid-128; vg_s[jj] = part[256+jj] + part[384+jj] + bv[jj]; }
        __syncthreads();
        {
            int h = tid >> 7, j2 = tid & 127;
            float a = 0.f;
            #pragma unroll
            for (int d=0;d<32;d++) a = fmaf(vg_s[h*32+d], Wgo[(h*32+d)*128+j2], a);
            g_vgo[((size_t)b*25 + t*4 + h)*128 + j2] = a;
        }
        if (t==0 && tid<128) g_vgo[((size_t)b*25 + 24)*128 + tid] = bgo[tid];
    } else if (bid == 96){
        if (tid == 0){ g_tkt[0]=0; g_tkt[1]=0; g_tkt[2]=0; g_tkt[3]=0; }
        float* W1t = smp;
        for (int e=tid;e<4096;e+=512) W1t[e] = lng[e>>6]*Wm1[e];
        __syncthreads();
        for (int e=tid;e<8192;e+=512){
            int k=e>>6, j=e&63;
            g_Wpack[k*328 + j]      = Wql[e];
            g_Wpack[k*328 + 64 + j] = Wnbr[128+e];
        }
        for (int e=tid;e<16384;e+=512){
            int k=e>>7, j=e&127;
            g_Wpack[k*328 + 128 + j] = Wqg[e];
        }
        for (int e=tid;e<8192;e+=512){
            int c=e>>6, j=e&63;
            float a = 0.f;
            #pragma unroll 4
            for (int i=0;i<64;i++) a = fmaf(Wnbr[128 + c*64 + i], W1t[i*64+j], a);
            g_Wpack[c*328 + 256 + j] = a;
        }
        if (tid < 256){
            int k = tid & 127, which = tid >> 7;
            float a = 0.f;
            for (int i=0;i<64;i++) a = fmaf(Wql[k*64+i], Wnbr[which*64 + i], a);
            g_Wpack[k*328 + 320 + which] = a;
        }
        if (tid < 128){
            for (int c=322;c<328;c++) g_Wpack[tid*328+c] = 0.f;
        }
        if (tid < 64){
            g_bpack[tid]      = bql[tid];
            g_bpack[64+tid]   = bnbr[tid];
            float bf = 0.f;
            for (int i=0;i<64;i++) bf = fmaf(bnbr[i], W1t[i*64+tid], bf);
            g_bpack[256+tid] = bf;
        }
        if (tid < 128) g_bpack[128+tid] = bqg[tid];
        if (tid == 0){
            float a0=0.f, a1=0.f;
            for (int i=0;i<64;i++){ a0 = fmaf(bql[i], Wnbr[i], a0); a1 = fmaf(bql[i], Wnbr[64+i], a1); }
            g_bpack[320] = a0; g_bpack[321] = a1;
        }
        if (tid < 64){
            int j = tid;
            float w0W=0.f, w1W=0.f, gcol=0.f, cadd=0.f;
            for (int i=0;i<192;i++){
                float w = Wm1[i*64+j];
                gcol += lng[i]*w;
                cadd += lnb[i]*w;
            }
            for (int i=0;i<64;i++){
                float w = lng[i]*Wm1[i*64+j];
                w0W += Wnbr[i]     * w;
                w1W += Wnbr[64+i]  * w;
            }
            g_cst[j]      = w0W;
            g_cst[64+j]   = w1W;
            g_cst[128+j]  = gcol;
            g_cst[192+j]  = cadd + bm1[j];
        }
    } else if (bid < 116){
        int n0 = (bid - 97) * 256;
        for (int e=tid;e<256*128;e+=512){
            int s = e>>7, k = e&127, n = n0 + s;
            if (n >= NS) break;
            g_q[n*128 + k] = (k<96) ? pos[n*96+k] : femb[fid[n]*32 + (k-96)];
        }
    } else {
        int tb = bid - 116;
        int nlo = tb*149, nhi = nlo+149; if (nhi > NS) nhi = NS;
        for (int n = nlo + tid; n < nhi; n += 512){
            unsigned mb = 0;
            #pragma unroll
            for (int b=0;b<16;b+=2){
                float2 xa = *(const float2*)(xf + ((size_t)b*NS + n)*2);
                float2 xb = *(const float2*)(xf + ((size_t)(b+1)*NS + n)*2);
                float4 o; o.x=xa.x; o.y=xa.y; o.z=xb.x; o.w=xb.y;
                *(float4*)(g_xq + n*32 + b*2) = o;
                if (mask[b*NS+n])     mb |= (1u<<b);
                if (mask[(b+1)*NS+n]) mb |= (1u<<(b+1));
            }
            g_mb[n] = mb;
        }
    }

    gbar(0);

    // ===================== PHASE B: GEMM tiles + folds =====================
    {
        float* AT = smp;            // 8704
        float* Ws = smp + 8704;     // 8192
        for (;;){
            __syncthreads();
            if (tid == 0) s_t = (int)atomicAdd(&g_tkt[0], 1);
            __syncthreads();
            int tt = s_t;
            if (tt >= 450) break;
            int n0 = (tt/6)*64, c0 = (tt%6)*64;
            for (int e=tid*4;e<8192;e+=2048){
                int s = e>>7, k = e&127, n = n0+s;
                float4 v;
                if (n < NS) v = *(const float4*)(g_q + n*128 + k);
                else { v.x=0.f; v.y=0.f; v.z=0.f; v.w=0.f; }
                AT[(k  )*68 + s] = v.x;
                AT[(k+1)*68 + s] = v.y;
                AT[(k+2)*68 + s] = v.z;
                AT[(k+3)*68 + s] = v.w;
            }
            for (int e=tid*4;e<8192;e+=2048){
                int k = e>>6, cc = e&63;
                *(float4*)(Ws + e) = *(const float4*)(g_Wpack + k*328 + c0 + cc);
            }
            __syncthreads();

            int cg = tid & 15, sg = tid >> 4;
            const float4* Wb = (const float4*)Ws + cg;
            float acc[2][4];
            #pragma unroll
            for (int s=0;s<2;s++){ acc[s][0]=0.f; acc[s][1]=0.f; acc[s][2]=0.f; acc[s][3]=0.f; }
            #pragma unroll 4
            for (int k=0;k<128;k++){
                float4 w = Wb[k*16];
                float a0 = AT[k*68 + sg*2];
                float a1 = AT[k*68 + sg*2 + 1];
                acc[0][0] = fmaf(a0, w.x, acc[0][0]);
                acc[0][1] = fmaf(a0, w.y, acc[0][1]);
                acc[0][2] = fmaf(a0, w.z, acc[0][2]);
                acc[0][3] = fmaf(a0, w.w, acc[0][3]);
                acc[1][0] = fmaf(a1, w.x, acc[1][0]);
                acc[1][1] = fmaf(a1, w.y, acc[1][1]);
                acc[1][2] = fmaf(a1, w.z, acc[1][2]);
                acc[1][3] = fmaf(a1, w.w, acc[1][3]);
            }
            #pragma unroll
            for (int s=0;s<2;s++){
                int n = n0 + sg*2 + s;
                if (n >= NS) continue;
                #pragma unroll
                for (int u=0;u<4;u++){
                    int c = c0 + cg*4 + u;
                    if (c >= 322) continue;
                    float v = acc[s][u] + g_bpack[c];
                    if (c < 64)        g_ql [n*64 + c]        = v;
                    else if (c < 128)  g_sp [n*64 + (c-64)]   = v;
                    else if (c < 256)  g_qg [n*128 + (c-128)] = v;
                    else if (c < 320)  g_spW[n*64 + (c-256)]  = v;
                    else if (c == 320) g_a0[n] = v;
                    else               g_a1[n] = v;
                }
            }
        }
        __syncthreads();
        float* w1bT = smp;   // 8448
        for (int e=tid;e<8192;e+=512){ int c=e>>6, j=e&63; w1bT[j*132+c] = lng[64+c]*Wm1[4096+e]; }
        __syncthreads();
        int c4 = lane*4;
        for (;;){
            int base;
            if (lane == 0) base = (int)atomicAdd(&g_tkt[1], 8);
            base = __shfl_sync(FULLM, base, 0);
            if (base >= 36000) break;
            #pragma unroll
            for (int k8=0;k8<8;k8++){
                int task = base + k8;
                if (task >= 36000) break;
                int b = task/2250, tt2 = task - b*2250;
                if (tt2 < 1600){
                    int i = tt2 >> 6, j = tt2 & 63;
                    float4 a = *(const float4*)(g_vgo + ((size_t)b*25+i)*128 + c4);
                    float4 w = *(const float4*)(w1bT + j*132 + c4);
                    float v = a.x*w.x + a.y*w.y + a.z*w.z + a.w*w.w;
                    v = wsum(v);
                    if (lane==0) g_vgoW[(b*25+i)*64 + j] = v;
                } else if (tt2 < 2225){
                    int p = tt2 - 1600, i1 = p/25, i2 = p - i1*25;
                    float4 a = *(const float4*)(g_vgo + ((size_t)b*25+i1)*128 + c4);
                    float4 c = *(const float4*)(g_vgo + ((size_t)b*25+i2)*128 + c4);
                    float v = a.x*c.x + a.y*c.y + a.z*c.z + a.w*c.w;
                    v = wsum(v);
                    if (lane==0) g_gram[b*625 + p] = v;
                } else {
                    int i = tt2 - 2225;
                    float4 a = *(const float4*)(g_vgo + ((size_t)b*25+i)*128 + c4);
                    float v = a.x + a.y + a.z + a.w;
                    v = wsum(v);
                    if (lane==0) g_sumv[b*25 + i] = v;
                }
            }
        }
    }

    gbar(1);

    // ===================== PHASE C: global softmax + Pg =====================
    {
        float* qs     = smp;              // 17024
        float* Ks     = smp + 17024;      // 768
        float* vgoW_s = smp + 17792;      // 1600
        float* gram_s = smp + 19392;      // 700
        float* sumv_s = smp + 20092;      // 32
        float* gax    = smp + 20124;      // 3456
        const float scale = 0.17677669529663687f;
        for (;;){
            __syncthreads();
            if (tid == 0) s_t = (int)atomicAdd(&g_tkt[2], 1);
            __syncthreads();
            int tt = s_t;
            if (tt >= 608) break;
            int b = tt & 15, n0 = (tt >> 4)*128;

            for (int e=tid;e<768;e+=512){
                int r=e>>5, k=e&31, h=r/6, t2=r%6;
                Ks[e] = g_kg[(b*NT+t2)*128 + h*32 + k];
            }
            for (int e=tid;e<1600;e+=512) vgoW_s[e] = g_vgoW[b*1600 + e];
            for (int e=tid;e<625;e+=512){ int i=e/25, jj=e-i*25; gram_s[i*28+jj] = g_gram[b*625 + e]; }
            if (tid < 25) sumv_s[tid] = g_sumv[b*25 + tid];
            for (int e=tid;e<16384;e+=512){
                int s=e>>7, k=e&127;
                int nr = (n0+s < NS) ? (n0+s) : (NS-1);
                qs[s*133+k] = g_qg[nr*128 + k];
            }
            __syncthreads();

            int s = tid & 127, q = tid >> 7;
            {
                float qv[32];
                #pragma unroll
                for (int k=0;k<32;k++) qv[k] = qs[s*133 + q*32 + k];
                float lg[6];
                #pragma unroll
                for (int t2=0;t2<6;t2++){
                    const float* kr = Ks + (q*6+t2)*32;
                    float a = 0.f;
                    #pragma unroll
                    for (int k=0;k<32;k++) a = fmaf(qv[k], kr[k], a);
                    lg[t2] = a;
                }
                float m = lg[0];
                #pragma unroll
                for (int t2=1;t2<6;t2++) m = fmaxf(m, lg[t2]);
                float den = 0.f, ex[6];
                #pragma unroll
                for (int t2=0;t2<6;t2++){ ex[t2] = __expf((lg[t2]-m)*scale); den += ex[t2]; }
                float inv = 1.f/den;
                #pragma unroll
                for (int t2=0;t2<6;t2++) gax[s*27 + t2*4 + q] = ex[t2]*inv;
            }
            __syncthreads();

            float ga[25];
            #pragma unroll
            for (int i=0;i<24;i++) ga[i] = gax[s*27 + i];
            ga[24] = 1.f;

            float4 pg4[4];
            {
                const float4* w24 = (const float4*)(vgoW_s + 24*64 + q*16);
                #pragma unroll
                for (int jj=0;jj<4;jj++) pg4[jj] = w24[jj];
            }
            #pragma unroll
            for (int i=0;i<24;i++){
                float g = ga[i];
                const float4* wr = (const float4*)(vgoW_s + i*64 + q*16);
                #pragma unroll
                for (int jj=0;jj<4;jj++){
                    float4 w = wr[jj];
                    pg4[jj].x = fmaf(g, w.x, pg4[jj].x);
                    pg4[jj].y = fmaf(g, w.y, pg4[jj].y);
                    pg4[jj].z = fmaf(g, w.z, pg4[jj].z);
                    pg4[jj].w = fmaf(g, w.w, pg4[jj].w);
                }
            }
            float sumg = 0.f, sumg2 = 0.f;
            if (q == 0){
                sumg = sumv_s[24];
                #pragma unroll
                for (int i=0;i<24;i++) sumg = fmaf(ga[i], sumv_s[i], sumg);
            }
            if (q == 1){
                #pragma unroll
                for (int i=0;i<25;i++){
                    float ti = gram_s[i*28 + 24];
                    #pragma unroll
                    for (int j4=0;j4<6;j4++){
                        float4 gv = *(const float4*)(gram_s + i*28 + j4*4);
                        ti = fmaf(gv.x, ga[j4*4+0], ti);
                        ti = fmaf(gv.y, ga[j4*4+1], ti);
                        ti = fmaf(gv.z, ga[j4*4+2], ti);
                        ti = fmaf(gv.w, ga[j4*4+3], ti);
                    }
                    sumg2 = fmaf(ga[i], ti, sumg2);
                }
            }
            if (n0 + s < NS){
                float* dst = g_pg + ((size_t)b*NS + (n0+s))*68;
                float4* d4 = (float4*)(dst + q*16);
                #pragma unroll
                for (int jj=0;jj<4;jj++) d4[jj] = pg4[jj];
                if (q == 0) dst[64] = sumg;
                if (q == 1) dst[65] = sumg2;
            }
        }
    }
}

// ------------------------- kDk: phase D standalone -------------------------
__global__ void __launch_bounds__(256) kDk(
    const int* __restrict__ knn, const float* __restrict__ Wnbr,
    const float* __restrict__ Wm2, const float* __restrict__ bm2,
    float* __restrict__ out)
{
    __shared__ float cst[448];
    __shared__ float rwT[8*1024];
    int tid = threadIdx.x;
    int lane = tid & 31;
    for (int e=tid;e<448;e+=256){
        float v;
        if (e < 128) v = Wnbr[e];
        else if (e < 384) v = g_cst[e-128];
        else v = Wm2[e-384];
        cst[e] = v;
    }
    __syncthreads();
    const float* w0_s  = cst;
    const float* w1_s  = cst + 64;
    const float* w0W_s = cst + 128;
    const float* w1W_s = cst + 192;
    const float* gcol_s= cst + 256;
    const float* cadd_s= cst + 320;
    const float* wm2_s = cst + 384;
    float bm2v = bm2[0];
    float* myT = rwT + (tid>>5)*1024;

    int n = blockIdx.x*8 + (tid>>5);
    if (n >= NS) return;

    int kj = 0; unsigned mkb = 0;
    if (lane < 16){ kj = knn[n*16 + lane]; mkb = g_mb[kj]; }
    unsigned mbn = g_mb[n];
    float a0 = g_a0[n], a1 = g_a1[n];
    float ql0 = g_ql[n*64 + lane], ql1 = g_ql[n*64 + 32 + lane];
    float rsp0[16], rsp1[16];
    #pragma unroll
    for (int k=0;k<16;k++){
        int j = __shfl_sync(FULLM, kj, k);
        rsp0[k] = g_sp[j*64 + lane];
        rsp1[k] = g_sp[j*64 + 32 + lane];
        myT[k*64 + lane]      = g_spW[j*64 + lane];
        myT[k*64 + 32 + lane] = g_spW[j*64 + 32 + lane];
    }
    float Sreg = 0.f;
    #pragma unroll
    for (int k0=0;k0<16;k0+=8){
        float p[8];
        #pragma unroll
        for (int u=0;u<8;u++) p[u] = fmaf(rsp0[k0+u], ql0, rsp1[k0+u]*ql1);
        wsumv<8>(p);
        #pragma unroll
        for (int u=0;u<8;u++) if (lane == k0+u) Sreg = p[u];
    }

    #pragma unroll
    for (int hb=0;hb<2;hb++){
        float4 xq4[4];
        #pragma unroll
        for (int u=0;u<4;u++){ xq4[u].x=0.f; xq4[u].y=0.f; xq4[u].z=0.f; xq4[u].w=0.f; }
        if (lane < 16){
            const float4* px = (const float4*)(g_xq + kj*32 + hb*16);
            #pragma unroll
            for (int u=0;u<4;u++) xq4[u] = px[u];
        }
        #pragma unroll
        for (int pg2=0;pg2<2;pg2++){
            float pr4[4];
            #pragma unroll
            for (int bp2=0;bp2<2;bp2++){
                int bp = pg2*2 + bp2;
                int b0 = hb*8 + bp*2, b1 = b0 + 1;
                const float* pgA = g_pg + ((size_t)b0*NS + n)*68;
                const float* pgB = g_pg + ((size_t)b1*NS + n)*68;
                float PgA0 = pgA[lane], PgA1 = pgA[32+lane];
                float sgA  = pgA[64],   sg2A = pgA[65];
                float PgB0 = pgB[lane], PgB1 = pgB[32+lane];
                float sgB  = pgB[64],   sg2B = pgB[65];

                float4 xv = xq4[bp];
                float x00 = xv.x, x01 = xv.y, x10 = xv.z, x11 = xv.w;
                float e0 = 0.f, e1 = 0.f;
                if (lane < 16){
                    float l0 = (Sreg + x00*a0 + x01*a1)*0.125f;
                    float l1 = (Sreg + x10*a0 + x11*a1)*0.125f;
                    e0 = ((mkb >> b0) & 1u) ? 1e-20f : __expf(l0);
                    e1 = ((mkb >> b1) & 1u) ? 1e-20f : __expf(l1);
                }
                float red[6];
                red[0] = e0; red[1] = e0*x00; red[2] = e0*x01;
                red[3] = e1; red[4] = e1*x10; red[5] = e1*x11;
                wsumv<6>(red);
                float inv0 = 1.f/red[0], inv1 = 1.f/red[3];
                float at0 = e0*inv0, at1 = e1*inv1;
                float al0 = red[1]*inv0, be0 = red[2]*inv0;
                float al1 = red[4]*inv1, be1 = red[5]*inv1;

                float L00 = al0*w0_s[lane]      + be0*w1_s[lane];
                float L01 = al0*w0_s[32+lane]   + be0*w1_s[32+lane];
                float P00 = al0*w0W_s[lane]     + be0*w1W_s[lane];
                float P01 = al0*w0W_s[32+lane]  + be0*w1W_s[32+lane];
                float L10 = al1*w0_s[lane]      + be1*w1_s[lane];
                float L11 = al1*w0_s[32+lane]   + be1*w1_s[32+lane];
                float P10 = al1*w0W_s[lane]     + be1*w1W_s[lane];
                float P11 = al1*w0W_s[32+lane]  + be1*w1W_s[32+lane];
                #pragma unroll
                for (int k=0;k<16;k++){
                    float ak0 = __shfl_sync(FULLM, at0, k);
                    float ak1 = __shfl_sync(FULLM, at1, k);
                    float w0v = myT[k*64 + lane];
                    float w1v = myT[k*64 + 32 + lane];
                    L00 = fmaf(ak0, rsp0[k], L00);
                    L01 = fmaf(ak0, rsp1[k], L01);
                    L10 = fmaf(ak1, rsp0[k], L10);
                    L11 = fmaf(ak1, rsp1[k], L11);
                    P00 = fmaf(ak0, w0v, P00);
                    P01 = fmaf(ak0, w1v, P01);
                    P10 = fmaf(ak1, w0v, P10);
                    P11 = fmaf(ak1, w1v, P11);
                }
                float rl[4];
                rl[0] = L00 + L01;
                rl[1] = L00*L00 + L01*L01;
                rl[2] = L10 + L11;
                rl[3] = L10*L10 + L11*L11;
                wsumv<4>(rl);

                float mean0 = (rl[0] + sgA)*(1.f/192.f);
                float var0  = (rl[1] + sg2A)*(1.f/192.f) - mean0*mean0;
                float rstd0 = rsqrtf(var0 + 1e-5f);
                float h00 = fmaf(rstd0, (P00+PgA0) - mean0*gcol_s[lane],    cadd_s[lane]);
                float h01 = fmaf(rstd0, (P01+PgA1) - mean0*gcol_s[32+lane], cadd_s[32+lane]);
                float g00 = 0.5f*h00*(1.f + erff(h00*0.70710678118654752f));
                float g01 = 0.5f*h01*(1.f + erff(h01*0.70710678118654752f));

                float mean1 = (rl[2] + sgB)*(1.f/192.f);
                float var1  = (rl[3] + sg2B)*(1.f/192.f) - mean1*mean1;
                float rstd1 = rsqrtf(var1 + 1e-5f);
                float h10 = fmaf(rstd1, (P10+PgB0) - mean1*gcol_s[lane],    cadd_s[lane]);
                float h11 = fmaf(rstd1, (P11+PgB1) - mean1*gcol_s[32+lane], cadd_s[32+lane]);
                float g10 = 0.5f*h10*(1.f + erff(h10*0.70710678118654752f));
                float g11 = 0.5f*h11*(1.f + erff(h11*0.70710678118654752f));

                pr4[bp2*2+0] = fmaf(g00, wm2_s[lane], g01*wm2_s[32+lane]);
                pr4[bp2*2+1] = fmaf(g10, wm2_s[lane], g11*wm2_s[32+lane]);
            }
            wsumv<4>(pr4);
            if (lane == 0){
                int bb = hb*8 + pg2*4;
                out[(bb+0)*NS + n] = ((mbn >> (bb+0)) & 1u) ? (pr4[0] + bm2v) : 0.f;
                out[(bb+1)*NS + n] = ((mbn >> (bb+1)) & 1u) ? (pr4[1] + bm2v) : 0.f;
                out[(bb+2)*NS + n] = ((mbn >> (bb+2)) & 1u) ? (pr4[2] + bm2v) : 0.f;
                out[(bb+3)*NS + n] = ((mbn >> (bb+3)) & 1u) ? (pr4[3] + bm2v) : 0.f;
            }
        }
    }
}

// ------------------------- launch -------------------------
extern "C" void kernel_launch(void* const* d_in, const int* in_sizes, int n_in,
                              void* d_out, int out_size){
    const float* xf    = (const float*)d_in[0];
    const float* latent= (const float*)d_in[1];
    const float* pos   = (const float*)d_in[2];
    const float* femb  = (const float*)d_in[3];
    const float* Wnbr  = (const float*)d_in[4];
    const float* bnbr  = (const float*)d_in[5];
    const float* Wql   = (const float*)d_in[6];
    const float* bql   = (const float*)d_in[7];
    const float* Wlat  = (const float*)d_in[8];
    const float* blat  = (const float*)d_in[9];
    const float* Wlf   = (const float*)d_in[10];
    const float* blf   = (const float*)d_in[11];
    const float* Wqg   = (const float*)d_in[12];
    const float* bqg   = (const float*)d_in[13];
    const float* Wk    = (const float*)d_in[14];
    const float* bk    = (const float*)d_in[15];
    const float* Wv    = (const float*)d_in[16];
    const float* bv    = (const float*)d_in[17];
    const float* Wgo   = (const float*)d_in[18];
    const float* bgo   = (const float*)d_in[19];
    const float* lng   = (const float*)d_in[20];
    const float* lnb   = (const float*)d_in[21];
    const float* Wm1   = (const float*)d_in[22];
    const float* bm1   = (const float*)d_in[23];
    const float* Wm2   = (const float*)d_in[24];
    const float* bm2   = (const float*)d_in[25];
    const int* mask    = (const int*)d_in[26];
    const int* knn     = (const int*)d_in[27];
    const int* fid     = (const int*)d_in[28];
    float* out = (float*)d_out;

    static int smem_sz = 23580*4;
    cudaFuncSetAttribute(kAll, cudaFuncAttributeMaxDynamicSharedMemorySize, smem_sz);

    kAll<<<NBLK, 512, smem_sz>>>(
        xf, latent, pos, femb, Wnbr, bnbr, Wql, bql, Wlat, blat, Wlf, blf,
        Wqg, bqg, Wk, bk, Wv, bv, Wgo, bgo, lng, lnb, Wm1, bm1,
        mask, fid);
    kDk<<<595, 256>>>(knn, Wnbr, Wm2, bm2, out);
}